// round 5
// baseline (speedup 1.0000x reference)
#include <cuda_runtime.h>
#include <cuda_bf16.h>
#include <math.h>
#include <stdint.h>

#define S_    4
#define N_    10000
#define L_    8
#define F_    128
#define G3_   384
#define OR_   64
#define SUB_  100
#define SEQ_  (S_*N_)
#define MB_   64
#define NT_   256
#define TILES_ (SEQ_/MB_)          // 625
#define NB_LOSS (S_*SUB_*(L_-1))
#define LOSS_CNT 179200.0f
#define APITCH 264
#define BPITCH 136
#define CHUNKE (128*BPITCH)

__device__ int      g_walksf[SEQ_*L_];
__device__ unsigned g_upk[SEQ_];
__device__ float    g_wg[8*G3_];
__device__ float    g_P[N_*G3_];
__device__ __nv_bfloat16 g_yw2[(size_t)L_*SEQ_*256];   // GRU1 out, split (hi|lo)
__device__ float    g_GI2[(size_t)L_*TILES_*3*NT_*32]; // GRU2 gi, fragment layout
__device__ float    g_yseq[L_-1][SEQ_*F_];
__device__ float    g_part1[NB_LOSS];
__device__ float    g_part2[NB_LOSS];
__device__ float    g_posw;
__device__ __nv_bfloat16 g_W1h[G3_*F_], g_W1l[G3_*F_];
__device__ __nv_bfloat16 g_W2h[G3_*F_], g_W2l[G3_*F_];
__device__ __nv_bfloat16 g_WXh[G3_*F_], g_WXl[G3_*F_];

__device__ __forceinline__ float sigf(float x) { return __fdividef(1.f, 1.f + __expf(-x)); }
__device__ __forceinline__ float tanh_s(float x) {
    float ax = fabsf(x); float e = __expf(-2.f*ax);
    return copysignf(__fdividef(1.f - e, 1.f + e), x);
}
__device__ __forceinline__ float softplusf(float x) {
    return fmaxf(x, 0.f) + log1pf(__expf(-fabsf(x)));
}
__device__ __forceinline__ float2 unpackbf(uint32_t u) {
    __nv_bfloat162 v = *(__nv_bfloat162*)&u;
    return make_float2(__bfloat162float(v.x), __bfloat162float(v.y));
}

__device__ __forceinline__ void mma16816(float c[4], uint32_t a0, uint32_t a1,
                                         uint32_t a2, uint32_t a3, uint32_t b0, uint32_t b1) {
    asm volatile("mma.sync.aligned.m16n8k16.row.col.f32.bf16.bf16.f32 "
                 "{%0,%1,%2,%3}, {%4,%5,%6,%7}, {%8,%9}, {%0,%1,%2,%3};\n"
                 : "+f"(c[0]), "+f"(c[1]), "+f"(c[2]), "+f"(c[3])
                 : "r"(a0), "r"(a1), "r"(a2), "r"(a3), "r"(b0), "r"(b1));
}

__device__ __forceinline__ void run_gemm(float (&acc)[2][4][4],
    const __nv_bfloat16* __restrict__ A, const __nv_bfloat16* __restrict__ B,
    int g, int tg2, int wc)
{
#pragma unroll
    for (int seg = 0; seg < 3; seg++) {
        const __nv_bfloat16* Ax = A + ((seg == 1) ? 128 : 0);
        const __nv_bfloat16* Bx = B + ((seg == 2) ? CHUNKE : 0);
#pragma unroll
        for (int ks = 0; ks < 8; ks++) {
            const int k0 = ks*16 + tg2;
            uint32_t a[2][4];
#pragma unroll
            for (int mt = 0; mt < 2; mt++) {
                const __nv_bfloat16* Ar = Ax + (mt*16 + g)*APITCH + k0;
                a[mt][0] = *(const uint32_t*)Ar;
                a[mt][1] = *(const uint32_t*)(Ar + 8*APITCH);
                a[mt][2] = *(const uint32_t*)(Ar + 8);
                a[mt][3] = *(const uint32_t*)(Ar + 8*APITCH + 8);
            }
#pragma unroll
            for (int nt = 0; nt < 4; nt++) {
                const __nv_bfloat16* Br = Bx + (wc*32 + nt*8 + g)*BPITCH + k0;
                uint32_t b0 = *(const uint32_t*)Br;
                uint32_t b1 = *(const uint32_t*)(Br + 8);
                mma16816(acc[0][nt], a[0][0], a[0][1], a[0][2], a[0][3], b0, b1);
                mma16816(acc[1][nt], a[1][0], a[1][1], a[1][2], a[1][3], b0, b1);
            }
        }
    }
}

__device__ __forceinline__ void stage_pair(__nv_bfloat16* dst,
    const __nv_bfloat16* __restrict__ hi, const __nv_bfloat16* __restrict__ lo,
    int jg, int tid)
{
    const __nv_bfloat16* s0 = hi + (size_t)jg*128*128;
    const __nv_bfloat16* s1 = lo + (size_t)jg*128*128;
#pragma unroll
    for (int it = 0; it < 8; it++) {
        int i = tid + it*NT_;
        int row = i >> 4, seg = (i & 15) << 3;
        *(uint4*)(dst + row*BPITCH + seg)          = *(const uint4*)(s0 + row*128 + seg);
        *(uint4*)(dst + CHUNKE + row*BPITCH + seg) = *(const uint4*)(s1 + row*128 + seg);
    }
}

// gi loader: IS2 -> GI2 fragment rows; else wg table rows (bias optional)
template<int IS2>
__device__ __forceinline__ void load_gi(float (&acc)[2][4][4], int jg, int t, int tile,
    const int* __restrict__ sh_i, const float* __restrict__ sh_bh, int addbias,
    int rbase, int g, int tg2, int wc)
{
    if constexpr (IS2) {
        const float* src = g_GI2 + ((((size_t)t*TILES_ + tile)*3 + jg)*NT_ + threadIdx.x)*32;
#pragma unroll
        for (int mt = 0; mt < 2; mt++)
#pragma unroll
            for (int nt = 0; nt < 4; nt++) {
                float4 v = *(const float4*)(src + (mt*4 + nt)*4);
                acc[mt][nt][0]=v.x; acc[mt][nt][1]=v.y; acc[mt][nt][2]=v.z; acc[mt][nt][3]=v.w;
            }
    } else {
#pragma unroll
        for (int mt = 0; mt < 2; mt++) {
            int u0 = (sh_i[rbase + mt*16 + g]     >> (4*t)) & 7;
            int u1 = (sh_i[rbase + mt*16 + g + 8] >> (4*t)) & 7;
#pragma unroll
            for (int nt = 0; nt < 4; nt++) {
                int cc = jg*F_ + wc*32 + nt*8 + tg2;
                float2 p0 = *(const float2*)&g_wg[u0*G3_ + cc];
                float2 p1 = *(const float2*)&g_wg[u1*G3_ + cc];
                acc[mt][nt][0]=p0.x; acc[mt][nt][1]=p0.y; acc[mt][nt][2]=p1.x; acc[mt][nt][3]=p1.y;
            }
        }
    }
    if (addbias) {
#pragma unroll
        for (int mt = 0; mt < 2; mt++)
#pragma unroll
            for (int nt = 0; nt < 4; nt++) {
                int cc = jg*F_ + wc*32 + nt*8 + tg2;
                float2 bh = *(const float2*)&sh_bh[cc];
                acc[mt][nt][0]+=bh.x; acc[mt][nt][1]+=bh.y; acc[mt][nt][2]+=bh.x; acc[mt][nt][3]+=bh.y;
            }
    }
}

// ---------------- preprocessing ----------------
__global__ void prep_kernel(const int* __restrict__ walks)
{
    int m = blockIdx.x * blockDim.x + threadIdx.x;
    if (m >= SEQ_) return;
    int w[L_];
#pragma unroll
    for (int p = 0; p < L_; p++) w[p] = walks[m*L_ + p];
    unsigned pk = 0;
#pragma unroll
    for (int t = 0; t < L_; t++) {
        int p = L_-1-t, wp = w[p], u = p;
#pragma unroll
        for (int q = L_-1; q >= 0; q--) if (w[q] == wp) u = q;
        g_walksf[m*L_ + t] = wp;
        pk |= ((unsigned)u) << (4*t);
    }
    g_upk[m] = pk;
}

__global__ void wg_kernel(const float* __restrict__ Wih_w, const float* __restrict__ bih_w)
{
    int j = threadIdx.x;
    float b = bih_w[j];
#pragma unroll
    for (int u = 0; u < 8; u++) g_wg[u*G3_ + j] = Wih_w[j*8 + u] + b;
}

__global__ void pack_kernel(const float* __restrict__ Whh_w, const float* __restrict__ Whh,
                            const float* __restrict__ Wih)
{
    int i = blockIdx.x * 256 + threadIdx.x;
    if (i >= G3_*F_) return;
    float a = Whh_w[i];
    __nv_bfloat16 h1 = __float2bfloat16(a);
    g_W1h[i] = h1; g_W1l[i] = __float2bfloat16(a - __bfloat162float(h1));
    float b = Whh[i];
    __nv_bfloat16 h2 = __float2bfloat16(b);
    g_W2h[i] = h2; g_W2l[i] = __float2bfloat16(b - __bfloat162float(h2));
    int n = i >> 7, k = i & 127;
    float c = Wih[n*256 + 128 + k];
    __nv_bfloat16 h3 = __float2bfloat16(c);
    g_WXh[i] = h3; g_WXl[i] = __float2bfloat16(c - __bfloat162float(h3));
}

// ---------------- P = h @ WihA^T + bih ----------------
__device__ __forceinline__ void gemm_tile(float acc[4][8], const float* __restrict__ sh_src,
    float* __restrict__ sh_w, const float* __restrict__ W, int wstride, int tx, int ty, int tid)
{
    for (int k0 = 0; k0 < F_; k0 += 32) {
        __syncthreads();
        {
            int j = tid >> 1, half = tid & 1;
            const float* src = W + (size_t)j*wstride + k0 + half*16;
#pragma unroll
            for (int q = 0; q < 4; q++) {
                float4 v = *(const float4*)(src + q*4);
                int kk = half*16 + q*4;
                sh_w[(kk+0)*128+j]=v.x; sh_w[(kk+1)*128+j]=v.y;
                sh_w[(kk+2)*128+j]=v.z; sh_w[(kk+3)*128+j]=v.w;
            }
        }
        __syncthreads();
        const float* s0 = sh_src + (ty*4+0)*132 + k0;
        const float* s1 = sh_src + (ty*4+1)*132 + k0;
        const float* s2 = sh_src + (ty*4+2)*132 + k0;
        const float* s3 = sh_src + (ty*4+3)*132 + k0;
#pragma unroll 8
        for (int kk = 0; kk < 32; kk++) {
            float4 wa = *(const float4*)&sh_w[kk*128 + tx*8];
            float4 wb = *(const float4*)&sh_w[kk*128 + tx*8 + 4];
            float h0=s0[kk], h1=s1[kk], h2=s2[kk], h3=s3[kk];
            acc[0][0]+=h0*wa.x; acc[0][1]+=h0*wa.y; acc[0][2]+=h0*wa.z; acc[0][3]+=h0*wa.w;
            acc[0][4]+=h0*wb.x; acc[0][5]+=h0*wb.y; acc[0][6]+=h0*wb.z; acc[0][7]+=h0*wb.w;
            acc[1][0]+=h1*wa.x; acc[1][1]+=h1*wa.y; acc[1][2]+=h1*wa.z; acc[1][3]+=h1*wa.w;
            acc[1][4]+=h1*wb.x; acc[1][5]+=h1*wb.y; acc[1][6]+=h1*wb.z; acc[1][7]+=h1*wb.w;
            acc[2][0]+=h2*wa.x; acc[2][1]+=h2*wa.y; acc[2][2]+=h2*wa.z; acc[2][3]+=h2*wa.w;
            acc[2][4]+=h2*wb.x; acc[2][5]+=h2*wb.y; acc[2][6]+=h2*wb.z; acc[2][7]+=h2*wb.w;
            acc[3][0]+=h3*wa.x; acc[3][1]+=h3*wa.y; acc[3][2]+=h3*wa.z; acc[3][3]+=h3*wa.w;
            acc[3][4]+=h3*wb.x; acc[3][5]+=h3*wb.y; acc[3][6]+=h3*wb.z; acc[3][7]+=h3*wb.w;
        }
    }
}

__global__ void __launch_bounds__(NT_) p_kernel(const float* __restrict__ h,
                                                const float* __restrict__ Wih,
                                                const float* __restrict__ bih)
{
    extern __shared__ float sm[];
    float* sh_s = sm;
    float* sh_w = sh_s + MB_*132;
    int tid = threadIdx.x, tx = tid & 15, ty = tid >> 4;
    int r0 = blockIdx.x * MB_;
    int jg = blockIdx.y;
    for (int i = tid; i < MB_*F_; i += NT_) {
        int r = i >> 7, k = i & 127, n = r0 + r;
        sh_s[r*132 + k] = (n < N_) ? h[(size_t)n*F_ + k] : 0.f;
    }
    __syncthreads();
    int jbase = jg*F_ + tx*8;
    float acc[4][8];
    {
        const float4* bp = (const float4*)(bih + jbase);
        float4 a = bp[0], b = bp[1];
        float bb[8] = {a.x,a.y,a.z,a.w,b.x,b.y,b.z,b.w};
#pragma unroll
        for (int mm = 0; mm < 4; mm++)
#pragma unroll
            for (int jj = 0; jj < 8; jj++) acc[mm][jj] = bb[jj];
    }
    gemm_tile(acc, sh_s, sh_w, Wih + (size_t)jg*F_*256, 256, tx, ty, tid);
#pragma unroll
    for (int mm = 0; mm < 4; mm++) {
        int n = r0 + ty*4 + mm;
        if (n < N_) {
            *(float4*)(g_P + (size_t)n*G3_ + jbase)   = make_float4(acc[mm][0],acc[mm][1],acc[mm][2],acc[mm][3]);
            *(float4*)(g_P + (size_t)n*G3_ + jbase+4) = make_float4(acc[mm][4],acc[mm][5],acc[mm][6],acc[mm][7]);
        }
    }
}

// ---------------- gix: GI2 = P[node] + x @ WXB^T (fragment layout) ----------------
__global__ void __launch_bounds__(NT_, 2) gix_kernel()
{
    extern __shared__ char smc[];
    __nv_bfloat16* sh_x2 = (__nv_bfloat16*)smc;                  // 33792 B
    __nv_bfloat16* sh_B  = (__nv_bfloat16*)(smc + 33792);        // 69632 B
    int* sh_i = (int*)(smc + 33792 + 69632);

    const int tid = threadIdx.x, wid = tid >> 5, lane = tid & 31;
    const int wr = wid & 1, wc = wid >> 1;
    const int g = lane >> 2, tg2 = (lane & 3)*2;
    const int rbase = wr*32;
    const int tile = blockIdx.x, jg = blockIdx.y;
    const int m0 = tile*MB_;

    stage_pair(sh_B, g_WXh, g_WXl, jg, tid);

#pragma unroll 1
    for (int t = 0; t < L_; t++) {
        __syncthreads();
#pragma unroll
        for (int it = 0; it < 8; it++) {
            int i = tid + it*NT_;
            int row = i >> 5, seg = (i & 31) << 3;
            *(uint4*)(sh_x2 + row*APITCH + seg) =
                *(const uint4*)(g_yw2 + ((size_t)t*SEQ_ + m0 + row)*256 + seg);
        }
        if (tid < MB_) sh_i[tid] = g_walksf[(size_t)(m0 + tid)*L_ + t];
        __syncthreads();

        float acc[2][4][4];
#pragma unroll
        for (int mt = 0; mt < 2; mt++) {
            int i0 = sh_i[rbase + mt*16 + g], i1 = sh_i[rbase + mt*16 + g + 8];
#pragma unroll
            for (int nt = 0; nt < 4; nt++) {
                int cc = jg*F_ + wc*32 + nt*8 + tg2;
                float2 p0 = *(const float2*)&g_P[(size_t)i0*G3_ + cc];
                float2 p1 = *(const float2*)&g_P[(size_t)i1*G3_ + cc];
                acc[mt][nt][0]=p0.x; acc[mt][nt][1]=p0.y; acc[mt][nt][2]=p1.x; acc[mt][nt][3]=p1.y;
            }
        }
        run_gemm(acc, sh_x2 + rbase*APITCH, sh_B, g, tg2, wc);

        float* dst = g_GI2 + ((((size_t)t*TILES_ + tile)*3 + jg)*NT_ + tid)*32;
#pragma unroll
        for (int mt = 0; mt < 2; mt++)
#pragma unroll
            for (int nt = 0; nt < 4; nt++)
                *(float4*)(dst + (mt*4 + nt)*4) =
                    make_float4(acc[mt][nt][0], acc[mt][nt][1], acc[mt][nt][2], acc[mt][nt][3]);
    }
}

// ---------------- fused tensor-core GRU (h-GEMM only; gate order r,n,z) -------
template<int IS2>
__global__ void __launch_bounds__(NT_, 2) gruT_kernel(const float* __restrict__ bhh,
                                                      float* __restrict__ hT_out)
{
    extern __shared__ char smc[];
    __nv_bfloat16* sh_h2 = (__nv_bfloat16*)smc;                  // 33792 B
    __nv_bfloat16* sh_B  = (__nv_bfloat16*)(smc + 33792);        // 69632 B
    float* sh_bh = (float*)(smc + 33792 + 69632);
    int*   sh_i  = (int*)(sh_bh + G3_);

    const int tid = threadIdx.x, wid = tid >> 5, lane = tid & 31;
    const int wr = wid & 1, wc = wid >> 1;
    const int g = lane >> 2, tg2 = (lane & 3)*2;
    const int rbase = wr*32;
    const int tile = blockIdx.x;
    const int m0 = tile*MB_;

    const __nv_bfloat16* WHi = IS2 ? g_W2h : g_W1h;
    const __nv_bfloat16* WHl = IS2 ? g_W2l : g_W1l;

    for (int i = tid; i < G3_; i += NT_) sh_bh[i] = bhh[i];
    if constexpr (IS2) {
#pragma unroll
        for (int it = 0; it < 8; it++) {
            int i = tid + it*NT_;
            int row = i >> 5, seg = (i & 31) << 3;
            *(uint4*)(sh_h2 + row*APITCH + seg) =
                *(const uint4*)(g_yw2 + ((size_t)(L_-1)*SEQ_ + m0 + row)*256 + seg);
        }
    } else {
        for (int i = tid; i < MB_*APITCH/2; i += NT_) ((uint32_t*)sh_h2)[i] = 0u;
        if (tid < MB_) sh_i[tid] = (int)g_upk[m0 + tid];
    }

#pragma unroll 1
    for (int t = 0; t < L_; t++) {
        const bool doH = IS2 || (t > 0);
        float nn[2][4][4];
        {
            // ---- gate r (jg=0) ----
            float rr[2][4][4];
            __syncthreads();
            if (doH) stage_pair(sh_B, WHi, WHl, 0, tid);
            __syncthreads();
            load_gi<IS2>(rr, 0, t, tile, sh_i, sh_bh, 1, rbase, g, tg2, wc);
            if (doH) run_gemm(rr, sh_h2 + rbase*APITCH, sh_B, g, tg2, wc);
#pragma unroll
            for (int mt=0; mt<2; mt++)
#pragma unroll
                for (int nt=0; nt<4; nt++)
#pragma unroll
                    for (int q=0; q<4; q++) rr[mt][nt][q] = sigf(rr[mt][nt][q]);

            // ---- gate n (jg=2) ----
            __syncthreads();
            if (doH) stage_pair(sh_B, WHi, WHl, 2, tid);
            __syncthreads();
            float acci[2][4][4], acch[2][4][4];
            load_gi<IS2>(acci, 2, t, tile, sh_i, nullptr, 0, rbase, g, tg2, wc);
#pragma unroll
            for (int mt=0; mt<2; mt++)
#pragma unroll
                for (int nt=0; nt<4; nt++) {
                    int cc = 2*F_ + wc*32 + nt*8 + tg2;
                    float2 bh = *(const float2*)&sh_bh[cc];
                    acch[mt][nt][0]=bh.x; acch[mt][nt][1]=bh.y;
                    acch[mt][nt][2]=bh.x; acch[mt][nt][3]=bh.y;
                }
            if (doH) run_gemm(acch, sh_h2 + rbase*APITCH, sh_B, g, tg2, wc);
#pragma unroll
            for (int mt=0; mt<2; mt++)
#pragma unroll
                for (int nt=0; nt<4; nt++)
#pragma unroll
                    for (int q=0; q<4; q++)
                        nn[mt][nt][q] = tanh_s(acci[mt][nt][q] + rr[mt][nt][q]*acch[mt][nt][q]);
        }

        // ---- gate z (jg=1) ----
        float zz[2][4][4];
        __syncthreads();
        if (doH) stage_pair(sh_B, WHi, WHl, 1, tid);
        __syncthreads();
        load_gi<IS2>(zz, 1, t, tile, sh_i, sh_bh, 1, rbase, g, tg2, wc);
        if (doH) run_gemm(zz, sh_h2 + rbase*APITCH, sh_B, g, tg2, wc);
#pragma unroll
        for (int mt=0; mt<2; mt++)
#pragma unroll
            for (int nt=0; nt<4; nt++)
#pragma unroll
                for (int q=0; q<4; q++) zz[mt][nt][q] = sigf(zz[mt][nt][q]);

        __syncthreads();   // all h reads complete before update
#pragma unroll
        for (int mt=0; mt<2; mt++)
#pragma unroll
            for (int nt=0; nt<4; nt++) {
                int cc = wc*32 + nt*8 + tg2;
#pragma unroll
                for (int p2=0; p2<2; p2++) {
                    int r = rbase + mt*16 + g + p2*8;
                    float n0 = nn[mt][nt][p2*2], n1 = nn[mt][nt][p2*2+1];
                    float z0 = zz[mt][nt][p2*2], z1 = zz[mt][nt][p2*2+1];
                    float2 hh = unpackbf(*(uint32_t*)&sh_h2[r*APITCH + cc]);
                    float2 hl = unpackbf(*(uint32_t*)&sh_h2[r*APITCH + 128 + cc]);
                    float h0 = (1.f - z0)*n0 + z0*(hh.x + hl.x);
                    float h1 = (1.f - z1)*n1 + z1*(hh.y + hl.y);
                    __nv_bfloat16 s0 = __float2bfloat16(h0), s1 = __float2bfloat16(h1);
                    __nv_bfloat162 hv; hv.x = s0; hv.y = s1;
                    uint32_t hiv = *(uint32_t*)&hv;
                    __nv_bfloat162 lv = __floats2bfloat162_rn(h0 - __bfloat162float(s0),
                                                              h1 - __bfloat162float(s1));
                    uint32_t lov = *(uint32_t*)&lv;
                    *(uint32_t*)&sh_h2[r*APITCH + cc] = hiv;
                    *(uint32_t*)&sh_h2[r*APITCH + 128 + cc] = lov;
                    if constexpr (IS2) {
                        float* dst = (t < L_-1) ? (g_yseq[t] + ((size_t)(m0+r))*F_ + cc)
                                                : (hT_out   + ((size_t)(m0+r))*F_ + cc);
                        *(float2*)dst = make_float2(h0, h1);
                    } else {
                        size_t base = ((size_t)t*SEQ_ + m0 + r)*256 + cc;
                        *(uint32_t*)&g_yw2[base]       = hiv;
                        *(uint32_t*)&g_yw2[base + 128] = lov;
                    }
                }
            }
    }
}

// ---------------- loss ----------------
__global__ void lsum_kernel(const int* __restrict__ idxs, const float* __restrict__ y0)
{
    int b = blockIdx.x;
    int t = b % (L_-1), j = (b/(L_-1)) % SUB_, s = b/((L_-1)*SUB_);
    int seq = s*N_ + idxs[j];
    int node = g_walksf[(size_t)seq*L_ + t + 1];
    int o = threadIdx.x;
    __shared__ float red[OR_];
    red[o] = y0[(size_t)node*OR_ + o]; __syncthreads();
    for (int st = OR_/2; st > 0; st >>= 1) { if (o < st) red[o] += red[o+st]; __syncthreads(); }
    if (o == 0) g_part1[b] = red[0];
}

__global__ void lred1_kernel()
{
    __shared__ float red[256];
    int tid = threadIdx.x; float s = 0.f;
    for (int i = tid; i < NB_LOSS; i += 256) s += g_part1[i];
    red[tid] = s; __syncthreads();
    for (int st = 128; st > 0; st >>= 1) { if (tid < st) red[tid] += red[tid+st]; __syncthreads(); }
    if (tid == 0) g_posw = LOSS_CNT / red[0];
}

__global__ void lbce_kernel(const int* __restrict__ idxs, const float* __restrict__ y0,
                            const float* __restrict__ Wss, const float* __restrict__ bss)
{
    int b = blockIdx.x;
    int t = b % (L_-1), j = (b/(L_-1)) % SUB_, s = b/((L_-1)*SUB_);
    int seq = s*N_ + idxs[j];
    __shared__ float yrow[F_];
    int o = threadIdx.x;
    yrow[o]      = g_yseq[t][(size_t)seq*F_ + o];
    yrow[o + 64] = g_yseq[t][(size_t)seq*F_ + o + 64];
    __syncthreads();
    float acc = bss[o];
    const float4* wrp = (const float4*)(Wss + (size_t)o*F_);
#pragma unroll 8
    for (int k = 0; k < F_/4; k++) {
        float4 w = wrp[k];
        acc += yrow[k*4]*w.x + yrow[k*4+1]*w.y + yrow[k*4+2]*w.z + yrow[k*4+3]*w.w;
    }
    int node = g_walksf[(size_t)seq*L_ + t + 1];
    float yt = y0[(size_t)node*OR_ + o];
    float term = g_posw * yt * softplusf(-acc) + (1.f - yt) * softplusf(acc);
    __shared__ float red[OR_];
    red[o] = term; __syncthreads();
    for (int st = OR_/2; st > 0; st >>= 1) { if (o < st) red[o] += red[o+st]; __syncthreads(); }
    if (o == 0) g_part2[b] = red[0];
}

__global__ void lred2_kernel(float* __restrict__ dst)
{
    __shared__ float red[256];
    int tid = threadIdx.x; float s = 0.f;
    for (int i = tid; i < NB_LOSS; i += 256) s += g_part2[i];
    red[tid] = s; __syncthreads();
    for (int st = 128; st > 0; st >>= 1) { if (tid < st) red[tid] += red[tid+st]; __syncthreads(); }
    if (tid == 0) *dst = red[0] / LOSS_CNT;
}

// ---------------- launch ----------------
extern "C" void kernel_launch(void* const* d_in, const int* in_sizes, int n_in,
                              void* d_out, int out_size)
{
    const float* h     = (const float*)d_in[0];
    const float* y0    = (const float*)d_in[1];
    const float* Wih_w = (const float*)d_in[2];
    const float* Whh_w = (const float*)d_in[3];
    const float* bih_w = (const float*)d_in[4];
    const float* bhh_w = (const float*)d_in[5];
    const float* Wih   = (const float*)d_in[6];
    const float* Whh   = (const float*)d_in[7];
    const float* bih   = (const float*)d_in[8];
    const float* bhh   = (const float*)d_in[9];
    const float* W_ss  = (const float*)d_in[10];
    const float* b_ss  = (const float*)d_in[11];
    const int*   walks = (const int*)d_in[12];
    const int*   idxs  = (const int*)d_in[13];
    float* out = (float*)d_out;

    const int SMEM_P   = (MB_*132 + 32*128) * 4;          // 50176
    const int SMEM_GIX = 33792 + 69632 + 256;             // 103680
    const int SMEM_GRU = 33792 + 69632 + G3_*4 + 256;     // 105216
    cudaFuncSetAttribute(p_kernel,       cudaFuncAttributeMaxDynamicSharedMemorySize, SMEM_P);
    cudaFuncSetAttribute(gix_kernel,     cudaFuncAttributeMaxDynamicSharedMemorySize, SMEM_GIX);
    cudaFuncSetAttribute(gruT_kernel<0>, cudaFuncAttributeMaxDynamicSharedMemorySize, SMEM_GRU);
    cudaFuncSetAttribute(gruT_kernel<1>, cudaFuncAttributeMaxDynamicSharedMemorySize, SMEM_GRU);

    prep_kernel<<<(SEQ_ + 255)/256, 256>>>(walks);
    wg_kernel<<<1, G3_>>>(Wih_w, bih_w);
    pack_kernel<<<(G3_*F_ + 255)/256, 256>>>(Whh_w, Whh, Wih);
    p_kernel<<<dim3((N_ + MB_-1)/MB_, 3), NT_, SMEM_P>>>(h, Wih, bih);
    gruT_kernel<0><<<TILES_, NT_, SMEM_GRU>>>(bhh_w, nullptr);
    gix_kernel<<<dim3(TILES_, 3), NT_, SMEM_GIX>>>();
    gruT_kernel<1><<<TILES_, NT_, SMEM_GRU>>>(bhh, out);
    lsum_kernel<<<NB_LOSS, OR_>>>(idxs, y0);
    lred1_kernel<<<1, 256>>>();
    lbce_kernel<<<NB_LOSS, OR_>>>(idxs, y0, W_ss, b_ss);
    lred2_kernel<<<1, 256>>>(out + (out_size - 1));
}

// round 6
// speedup vs baseline: 1.3565x; 1.3565x over previous
#include <cuda_runtime.h>
#include <cuda_bf16.h>
#include <math.h>
#include <stdint.h>

#define S_    4
#define N_    10000
#define L_    8
#define F_    128
#define G3_   384
#define OR_   64
#define SUB_  100
#define SEQ_  (S_*N_)
#define MB_   64
#define NT_   256
#define TILES_ (SEQ_/MB_)          // 625
#define NB_LOSS (S_*SUB_*(L_-1))
#define LOSS_CNT 179200.0f
#define APITCH 264
#define BPITCH 136
#define CHUNKE (128*BPITCH)

__device__ int      g_walksf[SEQ_*L_];
__device__ unsigned g_upk[SEQ_];
__device__ float    g_wg[8*G3_];
__device__ float    g_P[N_*G3_];
__device__ __nv_bfloat16 g_yw2[(size_t)L_*SEQ_*256];   // GRU1 out, split (hi|lo)
__device__ float    g_yseq[L_-1][SEQ_*F_];
__device__ float    g_part1[NB_LOSS];
__device__ float    g_part2[NB_LOSS];
__device__ float    g_posw;
__device__ __nv_bfloat16 g_W1h[G3_*F_], g_W1l[G3_*F_];
__device__ __nv_bfloat16 g_W2h[G3_*F_], g_W2l[G3_*F_];
__device__ __nv_bfloat16 g_WXh[G3_*F_], g_WXl[G3_*F_];

__device__ __forceinline__ float sigf(float x) { return __fdividef(1.f, 1.f + __expf(-x)); }
__device__ __forceinline__ float tanh_s(float x) {
    float ax = fabsf(x); float e = __expf(-2.f*ax);
    return copysignf(__fdividef(1.f - e, 1.f + e), x);
}
__device__ __forceinline__ float softplusf(float x) {
    return fmaxf(x, 0.f) + log1pf(__expf(-fabsf(x)));
}
__device__ __forceinline__ float2 unpackbf(uint32_t u) {
    __nv_bfloat162 v = *(__nv_bfloat162*)&u;
    return make_float2(__bfloat162float(v.x), __bfloat162float(v.y));
}

__device__ __forceinline__ void mma16816(float c[4], uint32_t a0, uint32_t a1,
                                         uint32_t a2, uint32_t a3, uint32_t b0, uint32_t b1) {
    asm volatile("mma.sync.aligned.m16n8k16.row.col.f32.bf16.bf16.f32 "
                 "{%0,%1,%2,%3}, {%4,%5,%6,%7}, {%8,%9}, {%0,%1,%2,%3};\n"
                 : "+f"(c[0]), "+f"(c[1]), "+f"(c[2]), "+f"(c[3])
                 : "r"(a0), "r"(a1), "r"(a2), "r"(a3), "r"(b0), "r"(b1));
}

__device__ __forceinline__ void run_gemm(float (&acc)[2][4][4],
    const __nv_bfloat16* __restrict__ A, const __nv_bfloat16* __restrict__ B,
    int g, int tg2, int wc)
{
#pragma unroll
    for (int seg = 0; seg < 3; seg++) {
        const __nv_bfloat16* Ax = A + ((seg == 1) ? 128 : 0);
        const __nv_bfloat16* Bx = B + ((seg == 2) ? CHUNKE : 0);
#pragma unroll
        for (int ks = 0; ks < 8; ks++) {
            const int k0 = ks*16 + tg2;
            uint32_t a[2][4];
#pragma unroll
            for (int mt = 0; mt < 2; mt++) {
                const __nv_bfloat16* Ar = Ax + (mt*16 + g)*APITCH + k0;
                a[mt][0] = *(const uint32_t*)Ar;
                a[mt][1] = *(const uint32_t*)(Ar + 8*APITCH);
                a[mt][2] = *(const uint32_t*)(Ar + 8);
                a[mt][3] = *(const uint32_t*)(Ar + 8*APITCH + 8);
            }
#pragma unroll
            for (int nt = 0; nt < 4; nt++) {
                const __nv_bfloat16* Br = Bx + (wc*32 + nt*8 + g)*BPITCH + k0;
                uint32_t b0 = *(const uint32_t*)Br;
                uint32_t b1 = *(const uint32_t*)(Br + 8);
                mma16816(acc[0][nt], a[0][0], a[0][1], a[0][2], a[0][3], b0, b1);
                mma16816(acc[1][nt], a[1][0], a[1][1], a[1][2], a[1][3], b0, b1);
            }
        }
    }
}

// synchronous weight pair staging (GRU1)
__device__ __forceinline__ void stage_pair(__nv_bfloat16* dst,
    const __nv_bfloat16* __restrict__ hi, const __nv_bfloat16* __restrict__ lo,
    int jg, int tid)
{
    const __nv_bfloat16* s0 = hi + (size_t)jg*128*128;
    const __nv_bfloat16* s1 = lo + (size_t)jg*128*128;
#pragma unroll
    for (int it = 0; it < 8; it++) {
        int i = tid + it*NT_;
        int row = i >> 4, seg = (i & 15) << 3;
        *(uint4*)(dst + row*BPITCH + seg)          = *(const uint4*)(s0 + row*128 + seg);
        *(uint4*)(dst + CHUNKE + row*BPITCH + seg) = *(const uint4*)(s1 + row*128 + seg);
    }
}

// async (cp.async.cg 16B) weight pair staging (GRU2)
__device__ __forceinline__ void cpa16(uint32_t d, const void* s) {
    asm volatile("cp.async.cg.shared.global [%0], [%1], 16;\n" :: "r"(d), "l"(s));
}
__device__ __forceinline__ void stage_async(uint32_t dstB,
    const __nv_bfloat16* __restrict__ hi, const __nv_bfloat16* __restrict__ lo,
    int jg, int tid)
{
    const __nv_bfloat16* s0 = hi + (size_t)jg*128*128;
    const __nv_bfloat16* s1 = lo + (size_t)jg*128*128;
#pragma unroll
    for (int it = 0; it < 8; it++) {
        int i = tid + it*NT_;
        int row = i >> 4, seg = (i & 15) << 3;
        uint32_t d = dstB + (uint32_t)(row*BPITCH + seg)*2u;
        cpa16(d, s0 + row*128 + seg);
        cpa16(d + (uint32_t)(CHUNKE*2), s1 + row*128 + seg);
    }
}
__device__ __forceinline__ void cp_wait_all() {
    asm volatile("cp.async.commit_group;\n");
    asm volatile("cp.async.wait_group 0;\n" ::: "memory");
}

// GRU1 gi loader: wg table from global (L1-resident), bias optional
__device__ __forceinline__ void load_gi1(float (&acc)[2][4][4], int jg, int t,
    const int* __restrict__ sh_i, const float* __restrict__ sh_bh, int addbias,
    int rbase, int g, int tg2, int wc)
{
#pragma unroll
    for (int mt = 0; mt < 2; mt++) {
        int u0 = (sh_i[rbase + mt*16 + g]     >> (4*t)) & 7;
        int u1 = (sh_i[rbase + mt*16 + g + 8] >> (4*t)) & 7;
#pragma unroll
        for (int nt = 0; nt < 4; nt++) {
            int cc = jg*F_ + wc*32 + nt*8 + tg2;
            float2 p0 = *(const float2*)&g_wg[u0*G3_ + cc];
            float2 p1 = *(const float2*)&g_wg[u1*G3_ + cc];
            acc[mt][nt][0]=p0.x; acc[mt][nt][1]=p0.y; acc[mt][nt][2]=p1.x; acc[mt][nt][3]=p1.y;
            if (addbias) {
                float2 bh = *(const float2*)&sh_bh[cc];
                acc[mt][nt][0]+=bh.x; acc[mt][nt][1]+=bh.y; acc[mt][nt][2]+=bh.x; acc[mt][nt][3]+=bh.y;
            }
        }
    }
}

// GRU2 gi loader: P gather, bias optional
__device__ __forceinline__ void load_gi2(float (&acc)[2][4][4], int jg,
    const int* __restrict__ sh_i, const float* __restrict__ sh_bh, int addbias,
    int rbase, int g, int tg2, int wc)
{
#pragma unroll
    for (int mt = 0; mt < 2; mt++) {
        int i0 = sh_i[rbase + mt*16 + g], i1 = sh_i[rbase + mt*16 + g + 8];
#pragma unroll
        for (int nt = 0; nt < 4; nt++) {
            int cc = jg*F_ + wc*32 + nt*8 + tg2;
            float2 p0 = *(const float2*)&g_P[(size_t)i0*G3_ + cc];
            float2 p1 = *(const float2*)&g_P[(size_t)i1*G3_ + cc];
            acc[mt][nt][0]=p0.x; acc[mt][nt][1]=p0.y; acc[mt][nt][2]=p1.x; acc[mt][nt][3]=p1.y;
            if (addbias) {
                float2 bh = *(const float2*)&sh_bh[cc];
                acc[mt][nt][0]+=bh.x; acc[mt][nt][1]+=bh.y; acc[mt][nt][2]+=bh.x; acc[mt][nt][3]+=bh.y;
            }
        }
    }
}

// ---------------- preprocessing ----------------
__global__ void prep_kernel(const int* __restrict__ walks)
{
    int m = blockIdx.x * blockDim.x + threadIdx.x;
    if (m >= SEQ_) return;
    int w[L_];
#pragma unroll
    for (int p = 0; p < L_; p++) w[p] = walks[m*L_ + p];
    unsigned pk = 0;
#pragma unroll
    for (int t = 0; t < L_; t++) {
        int p = L_-1-t, wp = w[p], u = p;
#pragma unroll
        for (int q = L_-1; q >= 0; q--) if (w[q] == wp) u = q;
        g_walksf[m*L_ + t] = wp;
        pk |= ((unsigned)u) << (4*t);
    }
    g_upk[m] = pk;
}

__global__ void wg_kernel(const float* __restrict__ Wih_w, const float* __restrict__ bih_w)
{
    int j = threadIdx.x;
    float b = bih_w[j];
#pragma unroll
    for (int u = 0; u < 8; u++) g_wg[u*G3_ + j] = Wih_w[j*8 + u] + b;
}

__global__ void pack_kernel(const float* __restrict__ Whh_w, const float* __restrict__ Whh,
                            const float* __restrict__ Wih)
{
    int i = blockIdx.x * 256 + threadIdx.x;
    if (i >= G3_*F_) return;
    float a = Whh_w[i];
    __nv_bfloat16 h1 = __float2bfloat16(a);
    g_W1h[i] = h1; g_W1l[i] = __float2bfloat16(a - __bfloat162float(h1));
    float b = Whh[i];
    __nv_bfloat16 h2 = __float2bfloat16(b);
    g_W2h[i] = h2; g_W2l[i] = __float2bfloat16(b - __bfloat162float(h2));
    int n = i >> 7, k = i & 127;
    float c = Wih[n*256 + 128 + k];
    __nv_bfloat16 h3 = __float2bfloat16(c);
    g_WXh[i] = h3; g_WXl[i] = __float2bfloat16(c - __bfloat162float(h3));
}

// ---------------- P = h @ WihA^T + bih ----------------
__device__ __forceinline__ void gemm_tile(float acc[4][8], const float* __restrict__ sh_src,
    float* __restrict__ sh_w, const float* __restrict__ W, int wstride, int tx, int ty, int tid)
{
    for (int k0 = 0; k0 < F_; k0 += 32) {
        __syncthreads();
        {
            int j = tid >> 1, half = tid & 1;
            const float* src = W + (size_t)j*wstride + k0 + half*16;
#pragma unroll
            for (int q = 0; q < 4; q++) {
                float4 v = *(const float4*)(src + q*4);
                int kk = half*16 + q*4;
                sh_w[(kk+0)*128+j]=v.x; sh_w[(kk+1)*128+j]=v.y;
                sh_w[(kk+2)*128+j]=v.z; sh_w[(kk+3)*128+j]=v.w;
            }
        }
        __syncthreads();
        const float* s0 = sh_src + (ty*4+0)*132 + k0;
        const float* s1 = sh_src + (ty*4+1)*132 + k0;
        const float* s2 = sh_src + (ty*4+2)*132 + k0;
        const float* s3 = sh_src + (ty*4+3)*132 + k0;
#pragma unroll 8
        for (int kk = 0; kk < 32; kk++) {
            float4 wa = *(const float4*)&sh_w[kk*128 + tx*8];
            float4 wb = *(const float4*)&sh_w[kk*128 + tx*8 + 4];
            float h0=s0[kk], h1=s1[kk], h2=s2[kk], h3=s3[kk];
            acc[0][0]+=h0*wa.x; acc[0][1]+=h0*wa.y; acc[0][2]+=h0*wa.z; acc[0][3]+=h0*wa.w;
            acc[0][4]+=h0*wb.x; acc[0][5]+=h0*wb.y; acc[0][6]+=h0*wb.z; acc[0][7]+=h0*wb.w;
            acc[1][0]+=h1*wa.x; acc[1][1]+=h1*wa.y; acc[1][2]+=h1*wa.z; acc[1][3]+=h1*wa.w;
            acc[1][4]+=h1*wb.x; acc[1][5]+=h1*wb.y; acc[1][6]+=h1*wb.z; acc[1][7]+=h1*wb.w;
            acc[2][0]+=h2*wa.x; acc[2][1]+=h2*wa.y; acc[2][2]+=h2*wa.z; acc[2][3]+=h2*wa.w;
            acc[2][4]+=h2*wb.x; acc[2][5]+=h2*wb.y; acc[2][6]+=h2*wb.z; acc[2][7]+=h2*wb.w;
            acc[3][0]+=h3*wa.x; acc[3][1]+=h3*wa.y; acc[3][2]+=h3*wa.z; acc[3][3]+=h3*wa.w;
            acc[3][4]+=h3*wb.x; acc[3][5]+=h3*wb.y; acc[3][6]+=h3*wb.z; acc[3][7]+=h3*wb.w;
        }
    }
}

__global__ void __launch_bounds__(NT_) p_kernel(const float* __restrict__ h,
                                                const float* __restrict__ Wih,
                                                const float* __restrict__ bih)
{
    extern __shared__ float sm[];
    float* sh_s = sm;
    float* sh_w = sh_s + MB_*132;
    int tid = threadIdx.x, tx = tid & 15, ty = tid >> 4;
    int r0 = blockIdx.x * MB_;
    int jg = blockIdx.y;
    for (int i = tid; i < MB_*F_; i += NT_) {
        int r = i >> 7, k = i & 127, n = r0 + r;
        sh_s[r*132 + k] = (n < N_) ? h[(size_t)n*F_ + k] : 0.f;
    }
    __syncthreads();
    int jbase = jg*F_ + tx*8;
    float acc[4][8];
    {
        const float4* bp = (const float4*)(bih + jbase);
        float4 a = bp[0], b = bp[1];
        float bb[8] = {a.x,a.y,a.z,a.w,b.x,b.y,b.z,b.w};
#pragma unroll
        for (int mm = 0; mm < 4; mm++)
#pragma unroll
            for (int jj = 0; jj < 8; jj++) acc[mm][jj] = bb[jj];
    }
    gemm_tile(acc, sh_s, sh_w, Wih + (size_t)jg*F_*256, 256, tx, ty, tid);
#pragma unroll
    for (int mm = 0; mm < 4; mm++) {
        int n = r0 + ty*4 + mm;
        if (n < N_) {
            *(float4*)(g_P + (size_t)n*G3_ + jbase)   = make_float4(acc[mm][0],acc[mm][1],acc[mm][2],acc[mm][3]);
            *(float4*)(g_P + (size_t)n*G3_ + jbase+4) = make_float4(acc[mm][4],acc[mm][5],acc[mm][6],acc[mm][7]);
        }
    }
}

// ---------------- GRU1: table gi, h-GEMM only, 2 blocks/SM ----------------
__global__ void __launch_bounds__(NT_, 2) gru1_kernel(const float* __restrict__ bhh)
{
    extern __shared__ char smc[];
    __nv_bfloat16* sh_h2 = (__nv_bfloat16*)smc;                  // 33792 B
    __nv_bfloat16* sh_B  = (__nv_bfloat16*)(smc + 33792);        // 69632 B
    float* sh_bh = (float*)(smc + 33792 + 69632);
    int*   sh_i  = (int*)(sh_bh + G3_);

    const int tid = threadIdx.x, wid = tid >> 5, lane = tid & 31;
    const int wr = wid & 1, wc = wid >> 1;
    const int g = lane >> 2, tg2 = (lane & 3)*2;
    const int rbase = wr*32;
    const int m0 = blockIdx.x*MB_;

    for (int i = tid; i < G3_; i += NT_) sh_bh[i] = bhh[i];
    for (int i = tid; i < MB_*APITCH/2; i += NT_) ((uint32_t*)sh_h2)[i] = 0u;
    if (tid < MB_) sh_i[tid] = (int)g_upk[m0 + tid];

#pragma unroll 1
    for (int t = 0; t < L_; t++) {
        const bool doH = (t > 0);
        float nn[2][4][4];
        {
            float rr[2][4][4];
            __syncthreads();
            if (doH) stage_pair(sh_B, g_W1h, g_W1l, 0, tid);
            __syncthreads();
            load_gi1(rr, 0, t, sh_i, sh_bh, 1, rbase, g, tg2, wc);
            if (doH) run_gemm(rr, sh_h2 + rbase*APITCH, sh_B, g, tg2, wc);
#pragma unroll
            for (int mt=0; mt<2; mt++)
#pragma unroll
                for (int nt=0; nt<4; nt++)
#pragma unroll
                    for (int q=0; q<4; q++) rr[mt][nt][q] = sigf(rr[mt][nt][q]);

            __syncthreads();
            if (doH) stage_pair(sh_B, g_W1h, g_W1l, 2, tid);
            __syncthreads();
            float acci[2][4][4], acch[2][4][4];
            load_gi1(acci, 2, t, sh_i, nullptr, 0, rbase, g, tg2, wc);
#pragma unroll
            for (int mt=0; mt<2; mt++)
#pragma unroll
                for (int nt=0; nt<4; nt++) {
                    int cc = 2*F_ + wc*32 + nt*8 + tg2;
                    float2 bh = *(const float2*)&sh_bh[cc];
                    acch[mt][nt][0]=bh.x; acch[mt][nt][1]=bh.y;
                    acch[mt][nt][2]=bh.x; acch[mt][nt][3]=bh.y;
                }
            if (doH) run_gemm(acch, sh_h2 + rbase*APITCH, sh_B, g, tg2, wc);
#pragma unroll
            for (int mt=0; mt<2; mt++)
#pragma unroll
                for (int nt=0; nt<4; nt++)
#pragma unroll
                    for (int q=0; q<4; q++)
                        nn[mt][nt][q] = tanh_s(acci[mt][nt][q] + rr[mt][nt][q]*acch[mt][nt][q]);
        }

        float zz[2][4][4];
        __syncthreads();
        if (doH) stage_pair(sh_B, g_W1h, g_W1l, 1, tid);
        __syncthreads();
        load_gi1(zz, 1, t, sh_i, sh_bh, 1, rbase, g, tg2, wc);
        if (doH) run_gemm(zz, sh_h2 + rbase*APITCH, sh_B, g, tg2, wc);
#pragma unroll
        for (int mt=0; mt<2; mt++)
#pragma unroll
            for (int nt=0; nt<4; nt++)
#pragma unroll
                for (int q=0; q<4; q++) zz[mt][nt][q] = sigf(zz[mt][nt][q]);

        __syncthreads();
#pragma unroll
        for (int mt=0; mt<2; mt++)
#pragma unroll
            for (int nt=0; nt<4; nt++) {
                int cc = wc*32 + nt*8 + tg2;
#pragma unroll
                for (int p2=0; p2<2; p2++) {
                    int r = rbase + mt*16 + g + p2*8;
                    float n0 = nn[mt][nt][p2*2], n1 = nn[mt][nt][p2*2+1];
                    float z0 = zz[mt][nt][p2*2], z1 = zz[mt][nt][p2*2+1];
                    float2 hh = unpackbf(*(uint32_t*)&sh_h2[r*APITCH + cc]);
                    float2 hl = unpackbf(*(uint32_t*)&sh_h2[r*APITCH + 128 + cc]);
                    float h0 = (1.f - z0)*n0 + z0*(hh.x + hl.x);
                    float h1 = (1.f - z1)*n1 + z1*(hh.y + hl.y);
                    __nv_bfloat16 s0 = __float2bfloat16(h0), s1 = __float2bfloat16(h1);
                    __nv_bfloat162 hv; hv.x = s0; hv.y = s1;
                    uint32_t hiv = *(uint32_t*)&hv;
                    __nv_bfloat162 lv = __floats2bfloat162_rn(h0 - __bfloat162float(s0),
                                                              h1 - __bfloat162float(s1));
                    uint32_t lov = *(uint32_t*)&lv;
                    *(uint32_t*)&sh_h2[r*APITCH + cc] = hiv;
                    *(uint32_t*)&sh_h2[r*APITCH + 128 + cc] = lov;
                    size_t base = ((size_t)t*SEQ_ + m0 + r)*256 + cc;
                    *(uint32_t*)&g_yw2[base]       = hiv;
                    *(uint32_t*)&g_yw2[base + 128] = lov;
                }
            }
    }
}

// ---------------- GRU2: fused x-GEMM + h-GEMM, cp.async staging ----------------
__global__ void __launch_bounds__(NT_, 1) gru2_kernel(const float* __restrict__ bhh,
                                                      float* __restrict__ hT_out)
{
    extern __shared__ char smc[];
    __nv_bfloat16* sh_h2 = (__nv_bfloat16*)smc;                  // 33792
    __nv_bfloat16* sh_x2 = (__nv_bfloat16*)(smc + 33792);        // 33792
    __nv_bfloat16* sh_B  = (__nv_bfloat16*)(smc + 67584);        // 139264 (4 chunks)
    float* sh_bh = (float*)(smc + 67584 + 139264);               // 1536
    int*   sh_i  = (int*)(sh_bh + G3_);                          // 256

    const int tid = threadIdx.x, wid = tid >> 5, lane = tid & 31;
    const int wr = wid & 1, wc = wid >> 1;
    const int g = lane >> 2, tg2 = (lane & 3)*2;
    const int rbase = wr*32;
    const int m0 = blockIdx.x*MB_;
    const uint32_t sBu = (uint32_t)__cvta_generic_to_shared(sh_B);
    __nv_bfloat16* sh_BH = sh_B + 2*CHUNKE;

    for (int i = tid; i < G3_; i += NT_) sh_bh[i] = bhh[i];
#pragma unroll
    for (int it = 0; it < 8; it++) {
        int i = tid + it*NT_;
        int row = i >> 5, seg = (i & 31) << 3;
        *(uint4*)(sh_h2 + row*APITCH + seg) =
            *(const uint4*)(g_yw2 + ((size_t)(L_-1)*SEQ_ + m0 + row)*256 + seg);
    }

#pragma unroll 1
    for (int t = 0; t < L_; t++) {
        __syncthreads();   // prior reads of sh_x2 / sh_B / sh_i complete
        // load x (split) + node indices; stage gate-r weights async
#pragma unroll
        for (int it = 0; it < 8; it++) {
            int i = tid + it*NT_;
            int row = i >> 5, seg = (i & 31) << 3;
            *(uint4*)(sh_x2 + row*APITCH + seg) =
                *(const uint4*)(g_yw2 + ((size_t)t*SEQ_ + m0 + row)*256 + seg);
        }
        if (tid < MB_) sh_i[tid] = g_walksf[(size_t)(m0 + tid)*L_ + t];
        stage_async(sBu, g_WXh, g_WXl, 0, tid);
        stage_async(sBu + 2u*CHUNKE*2u, g_W2h, g_W2l, 0, tid);
        __syncthreads();   // x, i visible (copies still in flight)

        float nn[2][4][4];
        {
            // ---- gate r ----
            float rr[2][4][4];
            load_gi2(rr, 0, sh_i, sh_bh, 1, rbase, g, tg2, wc);
            cp_wait_all();
            __syncthreads();
            run_gemm(rr, sh_x2 + rbase*APITCH, sh_B, g, tg2, wc);
            run_gemm(rr, sh_h2 + rbase*APITCH, sh_BH, g, tg2, wc);
#pragma unroll
            for (int mt=0; mt<2; mt++)
#pragma unroll
                for (int nt=0; nt<4; nt++)
#pragma unroll
                    for (int q=0; q<4; q++) rr[mt][nt][q] = sigf(rr[mt][nt][q]);

            // ---- gate n ----
            __syncthreads();
            stage_async(sBu, g_WXh, g_WXl, 2, tid);
            stage_async(sBu + 2u*CHUNKE*2u, g_W2h, g_W2l, 2, tid);
            float acci[2][4][4], acch[2][4][4];
            load_gi2(acci, 2, sh_i, nullptr, 0, rbase, g, tg2, wc);
#pragma unroll
            for (int mt=0; mt<2; mt++)
#pragma unroll
                for (int nt=0; nt<4; nt++) {
                    int cc = 2*F_ + wc*32 + nt*8 + tg2;
                    float2 bh = *(const float2*)&sh_bh[cc];
                    acch[mt][nt][0]=bh.x; acch[mt][nt][1]=bh.y;
                    acch[mt][nt][2]=bh.x; acch[mt][nt][3]=bh.y;
                }
            cp_wait_all();
            __syncthreads();
            run_gemm(acci, sh_x2 + rbase*APITCH, sh_B, g, tg2, wc);
            run_gemm(acch, sh_h2 + rbase*APITCH, sh_BH, g, tg2, wc);
#pragma unroll
            for (int mt=0; mt<2; mt++)
#pragma unroll
                for (int nt=0; nt<4; nt++)
#pragma unroll
                    for (int q=0; q<4; q++)
                        nn[mt][nt][q] = tanh_s(acci[mt][nt][q] + rr[mt][nt][q]*acch[mt][nt][q]);
        }

        // ---- gate z ----
        float zz[2][4][4];
        __syncthreads();
        stage_async(sBu, g_WXh, g_WXl, 1, tid);
        stage_async(sBu + 2u*CHUNKE*2u, g_W2h, g_W2l, 1, tid);
        load_gi2(zz, 1, sh_i, sh_bh, 1, rbase, g, tg2, wc);
        cp_wait_all();
        __syncthreads();
        run_gemm(zz, sh_x2 + rbase*APITCH, sh_B, g, tg2, wc);
        run_gemm(zz, sh_h2 + rbase*APITCH, sh_BH, g, tg2, wc);
#pragma unroll
        for (int mt=0; mt<2; mt++)
#pragma unroll
            for (int nt=0; nt<4; nt++)
#pragma unroll
                for (int q=0; q<4; q++) zz[mt][nt][q] = sigf(zz[mt][nt][q]);

        __syncthreads();   // all h reads complete
#pragma unroll
        for (int mt=0; mt<2; mt++)
#pragma unroll
            for (int nt=0; nt<4; nt++) {
                int cc = wc*32 + nt*8 + tg2;
#pragma unroll
                for (int p2=0; p2<2; p2++) {
                    int r = rbase + mt*16 + g + p2*8;
                    float n0 = nn[mt][nt][p2*2], n1 = nn[mt][nt][p2*2+1];
                    float z0 = zz[mt][nt][p2*2], z1 = zz[mt][nt][p2*2+1];
                    float2 hh = unpackbf(*(uint32_t*)&sh_h2[r*APITCH + cc]);
                    float2 hl = unpackbf(*(uint32_t*)&sh_h2[r*APITCH + 128 + cc]);
                    float h0 = (1.f - z0)*n0 + z0*(hh.x + hl.x);
                    float h1 = (1.f - z1)*n1 + z1*(hh.y + hl.y);
                    __nv_bfloat16 s0 = __float2bfloat16(h0), s1 = __float2bfloat16(h1);
                    __nv_bfloat162 hv; hv.x = s0; hv.y = s1;
                    uint32_t hiv = *(uint32_t*)&hv;
                    __nv_bfloat162 lv = __floats2bfloat162_rn(h0 - __bfloat162float(s0),
                                                              h1 - __bfloat162float(s1));
                    uint32_t lov = *(uint32_t*)&lv;
                    *(uint32_t*)&sh_h2[r*APITCH + cc] = hiv;
                    *(uint32_t*)&sh_h2[r*APITCH + 128 + cc] = lov;
                    float* dst = (t < L_-1) ? (g_yseq[t] + ((size_t)(m0+r))*F_ + cc)
                                            : (hT_out   + ((size_t)(m0+r))*F_ + cc);
                    *(float2*)dst = make_float2(h0, h1);
                }
            }
    }
}

// ---------------- loss ----------------
__global__ void lsum_kernel(const int* __restrict__ idxs, const float* __restrict__ y0)
{
    int b = blockIdx.x;
    int t = b % (L_-1), j = (b/(L_-1)) % SUB_, s = b/((L_-1)*SUB_);
    int seq = s*N_ + idxs[j];
    int node = g_walksf[(size_t)seq*L_ + t + 1];
    int o = threadIdx.x;
    __shared__ float red[OR_];
    red[o] = y0[(size_t)node*OR_ + o]; __syncthreads();
    for (int st = OR_/2; st > 0; st >>= 1) { if (o < st) red[o] += red[o+st]; __syncthreads(); }
    if (o == 0) g_part1[b] = red[0];
}

__global__ void lred1_kernel()
{
    __shared__ float red[256];
    int tid = threadIdx.x; float s = 0.f;
    for (int i = tid; i < NB_LOSS; i += 256) s += g_part1[i];
    red[tid] = s; __syncthreads();
    for (int st = 128; st > 0; st >>= 1) { if (tid < st) red[tid] += red[tid+st]; __syncthreads(); }
    if (tid == 0) g_posw = LOSS_CNT / red[0];
}

__global__ void lbce_kernel(const int* __restrict__ idxs, const float* __restrict__ y0,
                            const float* __restrict__ Wss, const float* __restrict__ bss)
{
    int b = blockIdx.x;
    int t = b % (L_-1), j = (b/(L_-1)) % SUB_, s = b/((L_-1)*SUB_);
    int seq = s*N_ + idxs[j];
    __shared__ float yrow[F_];
    int o = threadIdx.x;
    yrow[o]      = g_yseq[t][(size_t)seq*F_ + o];
    yrow[o + 64] = g_yseq[t][(size_t)seq*F_ + o + 64];
    __syncthreads();
    float acc = bss[o];
    const float4* wrp = (const float4*)(Wss + (size_t)o*F_);
#pragma unroll 8
    for (int k = 0; k < F_/4; k++) {
        float4 w = wrp[k];
        acc += yrow[k*4]*w.x + yrow[k*4+1]*w.y + yrow[k*4+2]*w.z + yrow[k*4+3]*w.w;
    }
    int node = g_walksf[(size_t)seq*L_ + t + 1];
    float yt = y0[(size_t)node*OR_ + o];
    float term = g_posw * yt * softplusf(-acc) + (1.f - yt) * softplusf(acc);
    __shared__ float red[OR_];
    red[o] = term; __syncthreads();
    for (int st = OR_/2; st > 0; st >>= 1) { if (o < st) red[o] += red[o+st]; __syncthreads(); }
    if (o == 0) g_part2[b] = red[0];
}

__global__ void lred2_kernel(float* __restrict__ dst)
{
    __shared__ float red[256];
    int tid = threadIdx.x; float s = 0.f;
    for (int i = tid; i < NB_LOSS; i += 256) s += g_part2[i];
    red[tid] = s; __syncthreads();
    for (int st = 128; st > 0; st >>= 1) { if (tid < st) red[tid] += red[tid+st]; __syncthreads(); }
    if (tid == 0) *dst = red[0] / LOSS_CNT;
}

// ---------------- launch ----------------
extern "C" void kernel_launch(void* const* d_in, const int* in_sizes, int n_in,
                              void* d_out, int out_size)
{
    const float* h     = (const float*)d_in[0];
    const float* y0    = (const float*)d_in[1];
    const float* Wih_w = (const float*)d_in[2];
    const float* Whh_w = (const float*)d_in[3];
    const float* bih_w = (const float*)d_in[4];
    const float* bhh_w = (const float*)d_in[5];
    const float* Wih   = (const float*)d_in[6];
    const float* Whh   = (const float*)d_in[7];
    const float* bih   = (const float*)d_in[8];
    const float* bhh   = (const float*)d_in[9];
    const float* W_ss  = (const float*)d_in[10];
    const float* b_ss  = (const float*)d_in[11];
    const int*   walks = (const int*)d_in[12];
    const int*   idxs  = (const int*)d_in[13];
    float* out = (float*)d_out;

    const int SMEM_P  = (MB_*132 + 32*128) * 4;            // 50176
    const int SMEM_G1 = 33792 + 69632 + G3_*4 + 256;       // 105216
    const int SMEM_G2 = 33792*2 + 4*CHUNKE*2 + G3_*4 + 256; // 208640
    cudaFuncSetAttribute(p_kernel,    cudaFuncAttributeMaxDynamicSharedMemorySize, SMEM_P);
    cudaFuncSetAttribute(gru1_kernel, cudaFuncAttributeMaxDynamicSharedMemorySize, SMEM_G1);
    cudaFuncSetAttribute(gru2_kernel, cudaFuncAttributeMaxDynamicSharedMemorySize, SMEM_G2);

    prep_kernel<<<(SEQ_ + 255)/256, 256>>>(walks);
    wg_kernel<<<1, G3_>>>(Wih_w, bih_w);
    pack_kernel<<<(G3_*F_ + 255)/256, 256>>>(Whh_w, Whh, Wih);
    p_kernel<<<dim3((N_ + MB_-1)/MB_, 3), NT_, SMEM_P>>>(h, Wih, bih);
    gru1_kernel<<<TILES_, NT_, SMEM_G1>>>(bhh_w);
    gru2_kernel<<<TILES_, NT_, SMEM_G2>>>(bhh, out);
    lsum_kernel<<<NB_LOSS, OR_>>>(idxs, y0);
    lred1_kernel<<<1, 256>>>();
    lbce_kernel<<<NB_LOSS, OR_>>>(idxs, y0, W_ss, b_ss);
    lred2_kernel<<<1, 256>>>(out + (out_size - 1));
}

// round 7
// speedup vs baseline: 1.5024x; 1.1075x over previous
#include <cuda_runtime.h>
#include <cuda_bf16.h>
#include <math.h>
#include <stdint.h>

#define S_    4
#define N_    10000
#define L_    8
#define F_    128
#define G3_   384
#define OR_   64
#define SUB_  100
#define SEQ_  (S_*N_)
#define MB_   64
#define NT_   256
#define TILES_ (SEQ_/MB_)          // 625
#define NB_LOSS (S_*SUB_*(L_-1))
#define LOSS_CNT 179200.0f
#define APITCH 264
#define BPITCH 136
#define CHUNKE (128*BPITCH)

__device__ int      g_walksf[SEQ_*L_];
__device__ unsigned g_upk[SEQ_];
__device__ float    g_wg[8*G3_];
__device__ float    g_P[N_*G3_];
__device__ __nv_bfloat16 g_yw2[(size_t)L_*SEQ_*256];   // GRU1 out, split (hi|lo)
__device__ float    g_yseq[L_-1][SEQ_*F_];
__device__ float    g_part1[NB_LOSS];
__device__ float    g_part2[NB_LOSS];
__device__ float    g_posw;
__device__ __nv_bfloat16 g_W1h[G3_*F_], g_W1l[G3_*F_];
__device__ __nv_bfloat16 g_W2h[G3_*F_], g_W2l[G3_*F_];
__device__ __nv_bfloat16 g_WXh[G3_*F_], g_WXl[G3_*F_];

__device__ __forceinline__ float sigf(float x) { return __fdividef(1.f, 1.f + __expf(-x)); }
__device__ __forceinline__ float tanh_s(float x) {
    float ax = fabsf(x); float e = __expf(-2.f*ax);
    return copysignf(__fdividef(1.f - e, 1.f + e), x);
}
__device__ __forceinline__ float softplusf(float x) {
    return fmaxf(x, 0.f) + log1pf(__expf(-fabsf(x)));
}
__device__ __forceinline__ float2 unpackbf(uint32_t u) {
    __nv_bfloat162 v = *(__nv_bfloat162*)&u;
    return make_float2(__bfloat162float(v.x), __bfloat162float(v.y));
}

__device__ __forceinline__ void mma16816(float c[4], uint32_t a0, uint32_t a1,
                                         uint32_t a2, uint32_t a3, uint32_t b0, uint32_t b1) {
    asm volatile("mma.sync.aligned.m16n8k16.row.col.f32.bf16.bf16.f32 "
                 "{%0,%1,%2,%3}, {%4,%5,%6,%7}, {%8,%9}, {%0,%1,%2,%3};\n"
                 : "+f"(c[0]), "+f"(c[1]), "+f"(c[2]), "+f"(c[3])
                 : "r"(a0), "r"(a1), "r"(a2), "r"(a3), "r"(b0), "r"(b1));
}

__device__ __forceinline__ void ldsm_x4(uint32_t& r0, uint32_t& r1, uint32_t& r2, uint32_t& r3,
                                        const void* p) {
    uint32_t a = (uint32_t)__cvta_generic_to_shared(p);
    asm volatile("ldmatrix.sync.aligned.m8n8.x4.shared.b16 {%0,%1,%2,%3}, [%4];"
                 : "=r"(r0), "=r"(r1), "=r"(r2), "=r"(r3) : "r"(a));
}

// acc[2][4][4] += A(32x256 split bf16, pitch APITCH) @ W^T
// Whi chunk at B, Wlo at B+CHUNKE. 3 segments (Ahi*Whi, Alo*Whi, Ahi*Wlo),
// all fragments loaded ONCE per ks via ldmatrix.x4.
__device__ __forceinline__ void run_gemm(float (&acc)[2][4][4],
    const __nv_bfloat16* __restrict__ A, const __nv_bfloat16* __restrict__ B,
    int lane, int wc)
{
    const int rl = lane & 15;            // row-in-16 selector
    const int kp = (lane >> 4) << 3;     // +8 k-offset for upper half-warp
#pragma unroll
    for (int ks = 0; ks < 8; ks++) {
        const int k0 = ks*16 + kp;
        uint32_t ah[2][4], al[2][4];
#pragma unroll
        for (int mt = 0; mt < 2; mt++) {
            const __nv_bfloat16* Ar = A + (mt*16 + rl)*APITCH + k0;
            ldsm_x4(ah[mt][0], ah[mt][1], ah[mt][2], ah[mt][3], Ar);
            ldsm_x4(al[mt][0], al[mt][1], al[mt][2], al[mt][3], Ar + 128);
        }
#pragma unroll
        for (int np = 0; np < 2; np++) {
            const __nv_bfloat16* Br = B + (wc*32 + np*16 + rl)*BPITCH + k0;
            uint32_t bh[4], bl[4];
            ldsm_x4(bh[0], bh[1], bh[2], bh[3], Br);
            ldsm_x4(bl[0], bl[1], bl[2], bl[3], Br + CHUNKE);
#pragma unroll
            for (int mt = 0; mt < 2; mt++) {
                // seg0: Ahi * Whi
                mma16816(acc[mt][np*2+0], ah[mt][0], ah[mt][1], ah[mt][2], ah[mt][3], bh[0], bh[2]);
                mma16816(acc[mt][np*2+1], ah[mt][0], ah[mt][1], ah[mt][2], ah[mt][3], bh[1], bh[3]);
                // seg1: Alo * Whi
                mma16816(acc[mt][np*2+0], al[mt][0], al[mt][1], al[mt][2], al[mt][3], bh[0], bh[2]);
                mma16816(acc[mt][np*2+1], al[mt][0], al[mt][1], al[mt][2], al[mt][3], bh[1], bh[3]);
                // seg2: Ahi * Wlo
                mma16816(acc[mt][np*2+0], ah[mt][0], ah[mt][1], ah[mt][2], ah[mt][3], bl[0], bl[2]);
                mma16816(acc[mt][np*2+1], ah[mt][0], ah[mt][1], ah[mt][2], ah[mt][3], bl[1], bl[3]);
            }
        }
    }
}

// synchronous weight pair staging (GRU1)
__device__ __forceinline__ void stage_pair(__nv_bfloat16* dst,
    const __nv_bfloat16* __restrict__ hi, const __nv_bfloat16* __restrict__ lo,
    int jg, int tid)
{
    const __nv_bfloat16* s0 = hi + (size_t)jg*128*128;
    const __nv_bfloat16* s1 = lo + (size_t)jg*128*128;
#pragma unroll
    for (int it = 0; it < 8; it++) {
        int i = tid + it*NT_;
        int row = i >> 4, seg = (i & 15) << 3;
        *(uint4*)(dst + row*BPITCH + seg)          = *(const uint4*)(s0 + row*128 + seg);
        *(uint4*)(dst + CHUNKE + row*BPITCH + seg) = *(const uint4*)(s1 + row*128 + seg);
    }
}

// async (cp.async.cg 16B) weight pair staging (GRU2)
__device__ __forceinline__ void cpa16(uint32_t d, const void* s) {
    asm volatile("cp.async.cg.shared.global [%0], [%1], 16;\n" :: "r"(d), "l"(s));
}
__device__ __forceinline__ void stage_async(uint32_t dstB,
    const __nv_bfloat16* __restrict__ hi, const __nv_bfloat16* __restrict__ lo,
    int jg, int tid)
{
    const __nv_bfloat16* s0 = hi + (size_t)jg*128*128;
    const __nv_bfloat16* s1 = lo + (size_t)jg*128*128;
#pragma unroll
    for (int it = 0; it < 8; it++) {
        int i = tid + it*NT_;
        int row = i >> 4, seg = (i & 15) << 3;
        uint32_t d = dstB + (uint32_t)(row*BPITCH + seg)*2u;
        cpa16(d, s0 + row*128 + seg);
        cpa16(d + (uint32_t)(CHUNKE*2), s1 + row*128 + seg);
    }
}
__device__ __forceinline__ void cp_wait_all() {
    asm volatile("cp.async.commit_group;\n");
    asm volatile("cp.async.wait_group 0;\n" ::: "memory");
}

// GRU1 gi loader
__device__ __forceinline__ void load_gi1(float (&acc)[2][4][4], int jg, int t,
    const int* __restrict__ sh_i, const float* __restrict__ sh_bh, int addbias,
    int rbase, int g, int tg2, int wc)
{
#pragma unroll
    for (int mt = 0; mt < 2; mt++) {
        int u0 = (sh_i[rbase + mt*16 + g]     >> (4*t)) & 7;
        int u1 = (sh_i[rbase + mt*16 + g + 8] >> (4*t)) & 7;
#pragma unroll
        for (int nt = 0; nt < 4; nt++) {
            int cc = jg*F_ + wc*32 + nt*8 + tg2;
            float2 p0 = *(const float2*)&g_wg[u0*G3_ + cc];
            float2 p1 = *(const float2*)&g_wg[u1*G3_ + cc];
            acc[mt][nt][0]=p0.x; acc[mt][nt][1]=p0.y; acc[mt][nt][2]=p1.x; acc[mt][nt][3]=p1.y;
            if (addbias) {
                float2 bh = *(const float2*)&sh_bh[cc];
                acc[mt][nt][0]+=bh.x; acc[mt][nt][1]+=bh.y; acc[mt][nt][2]+=bh.x; acc[mt][nt][3]+=bh.y;
            }
        }
    }
}

// GRU2 gi loader (P gather)
__device__ __forceinline__ void load_gi2(float (&acc)[2][4][4], int jg,
    const int* __restrict__ sh_i, const float* __restrict__ sh_bh, int addbias,
    int rbase, int g, int tg2, int wc)
{
#pragma unroll
    for (int mt = 0; mt < 2; mt++) {
        int i0 = sh_i[rbase + mt*16 + g], i1 = sh_i[rbase + mt*16 + g + 8];
#pragma unroll
        for (int nt = 0; nt < 4; nt++) {
            int cc = jg*F_ + wc*32 + nt*8 + tg2;
            float2 p0 = *(const float2*)&g_P[(size_t)i0*G3_ + cc];
            float2 p1 = *(const float2*)&g_P[(size_t)i1*G3_ + cc];
            acc[mt][nt][0]=p0.x; acc[mt][nt][1]=p0.y; acc[mt][nt][2]=p1.x; acc[mt][nt][3]=p1.y;
            if (addbias) {
                float2 bh = *(const float2*)&sh_bh[cc];
                acc[mt][nt][0]+=bh.x; acc[mt][nt][1]+=bh.y; acc[mt][nt][2]+=bh.x; acc[mt][nt][3]+=bh.y;
            }
        }
    }
}

// ---------------- preprocessing ----------------
__global__ void prep_kernel(const int* __restrict__ walks)
{
    int m = blockIdx.x * blockDim.x + threadIdx.x;
    if (m >= SEQ_) return;
    int w[L_];
#pragma unroll
    for (int p = 0; p < L_; p++) w[p] = walks[m*L_ + p];
    unsigned pk = 0;
#pragma unroll
    for (int t = 0; t < L_; t++) {
        int p = L_-1-t, wp = w[p], u = p;
#pragma unroll
        for (int q = L_-1; q >= 0; q--) if (w[q] == wp) u = q;
        g_walksf[m*L_ + t] = wp;
        pk |= ((unsigned)u) << (4*t);
    }
    g_upk[m] = pk;
}

__global__ void wg_kernel(const float* __restrict__ Wih_w, const float* __restrict__ bih_w)
{
    int j = threadIdx.x;
    float b = bih_w[j];
#pragma unroll
    for (int u = 0; u < 8; u++) g_wg[u*G3_ + j] = Wih_w[j*8 + u] + b;
}

__global__ void pack_kernel(const float* __restrict__ Whh_w, const float* __restrict__ Whh,
                            const float* __restrict__ Wih)
{
    int i = blockIdx.x * 256 + threadIdx.x;
    if (i >= G3_*F_) return;
    float a = Whh_w[i];
    __nv_bfloat16 h1 = __float2bfloat16(a);
    g_W1h[i] = h1; g_W1l[i] = __float2bfloat16(a - __bfloat162float(h1));
    float b = Whh[i];
    __nv_bfloat16 h2 = __float2bfloat16(b);
    g_W2h[i] = h2; g_W2l[i] = __float2bfloat16(b - __bfloat162float(h2));
    int n = i >> 7, k = i & 127;
    float c = Wih[n*256 + 128 + k];
    __nv_bfloat16 h3 = __float2bfloat16(c);
    g_WXh[i] = h3; g_WXl[i] = __float2bfloat16(c - __bfloat162float(h3));
}

// ---------------- P = h @ WihA^T + bih ----------------
__device__ __forceinline__ void gemm_tile(float acc[4][8], const float* __restrict__ sh_src,
    float* __restrict__ sh_w, const float* __restrict__ W, int wstride, int tx, int ty, int tid)
{
    for (int k0 = 0; k0 < F_; k0 += 32) {
        __syncthreads();
        {
            int j = tid >> 1, half = tid & 1;
            const float* src = W + (size_t)j*wstride + k0 + half*16;
#pragma unroll
            for (int q = 0; q < 4; q++) {
                float4 v = *(const float4*)(src + q*4);
                int kk = half*16 + q*4;
                sh_w[(kk+0)*128+j]=v.x; sh_w[(kk+1)*128+j]=v.y;
                sh_w[(kk+2)*128+j]=v.z; sh_w[(kk+3)*128+j]=v.w;
            }
        }
        __syncthreads();
        const float* s0 = sh_src + (ty*4+0)*132 + k0;
        const float* s1 = sh_src + (ty*4+1)*132 + k0;
        const float* s2 = sh_src + (ty*4+2)*132 + k0;
        const float* s3 = sh_src + (ty*4+3)*132 + k0;
#pragma unroll 8
        for (int kk = 0; kk < 32; kk++) {
            float4 wa = *(const float4*)&sh_w[kk*128 + tx*8];
            float4 wb = *(const float4*)&sh_w[kk*128 + tx*8 + 4];
            float h0=s0[kk], h1=s1[kk], h2=s2[kk], h3=s3[kk];
            acc[0][0]+=h0*wa.x; acc[0][1]+=h0*wa.y; acc[0][2]+=h0*wa.z; acc[0][3]+=h0*wa.w;
            acc[0][4]+=h0*wb.x; acc[0][5]+=h0*wb.y; acc[0][6]+=h0*wb.z; acc[0][7]+=h0*wb.w;
            acc[1][0]+=h1*wa.x; acc[1][1]+=h1*wa.y; acc[1][2]+=h1*wa.z; acc[1][3]+=h1*wa.w;
            acc[1][4]+=h1*wb.x; acc[1][5]+=h1*wb.y; acc[1][6]+=h1*wb.z; acc[1][7]+=h1*wb.w;
            acc[2][0]+=h2*wa.x; acc[2][1]+=h2*wa.y; acc[2][2]+=h2*wa.z; acc[2][3]+=h2*wa.w;
            acc[2][4]+=h2*wb.x; acc[2][5]+=h2*wb.y; acc[2][6]+=h2*wb.z; acc[2][7]+=h2*wb.w;
            acc[3][0]+=h3*wa.x; acc[3][1]+=h3*wa.y; acc[3][2]+=h3*wa.z; acc[3][3]+=h3*wa.w;
            acc[3][4]+=h3*wb.x; acc[3][5]+=h3*wb.y; acc[3][6]+=h3*wb.z; acc[3][7]+=h3*wb.w;
        }
    }
}

__global__ void __launch_bounds__(NT_) p_kernel(const float* __restrict__ h,
                                                const float* __restrict__ Wih,
                                                const float* __restrict__ bih)
{
    extern __shared__ float sm[];
    float* sh_s = sm;
    float* sh_w = sh_s + MB_*132;
    int tid = threadIdx.x, tx = tid & 15, ty = tid >> 4;
    int r0 = blockIdx.x * MB_;
    int jg = blockIdx.y;
    for (int i = tid; i < MB_*F_; i += NT_) {
        int r = i >> 7, k = i & 127, n = r0 + r;
        sh_s[r*132 + k] = (n < N_) ? h[(size_t)n*F_ + k] : 0.f;
    }
    __syncthreads();
    int jbase = jg*F_ + tx*8;
    float acc[4][8];
    {
        const float4* bp = (const float4*)(bih + jbase);
        float4 a = bp[0], b = bp[1];
        float bb[8] = {a.x,a.y,a.z,a.w,b.x,b.y,b.z,b.w};
#pragma unroll
        for (int mm = 0; mm < 4; mm++)
#pragma unroll
            for (int jj = 0; jj < 8; jj++) acc[mm][jj] = bb[jj];
    }
    gemm_tile(acc, sh_s, sh_w, Wih + (size_t)jg*F_*256, 256, tx, ty, tid);
#pragma unroll
    for (int mm = 0; mm < 4; mm++) {
        int n = r0 + ty*4 + mm;
        if (n < N_) {
            *(float4*)(g_P + (size_t)n*G3_ + jbase)   = make_float4(acc[mm][0],acc[mm][1],acc[mm][2],acc[mm][3]);
            *(float4*)(g_P + (size_t)n*G3_ + jbase+4) = make_float4(acc[mm][4],acc[mm][5],acc[mm][6],acc[mm][7]);
        }
    }
}

// ---------------- GRU1 ----------------
__global__ void __launch_bounds__(NT_, 2) gru1_kernel(const float* __restrict__ bhh)
{
    extern __shared__ char smc[];
    __nv_bfloat16* sh_h2 = (__nv_bfloat16*)smc;                  // 33792 B
    __nv_bfloat16* sh_B  = (__nv_bfloat16*)(smc + 33792);        // 69632 B
    float* sh_bh = (float*)(smc + 33792 + 69632);
    int*   sh_i  = (int*)(sh_bh + G3_);

    const int tid = threadIdx.x, wid = tid >> 5, lane = tid & 31;
    const int wr = wid & 1, wc = wid >> 1;
    const int g = lane >> 2, tg2 = (lane & 3)*2;
    const int rbase = wr*32;
    const int m0 = blockIdx.x*MB_;

    for (int i = tid; i < G3_; i += NT_) sh_bh[i] = bhh[i];
    for (int i = tid; i < MB_*APITCH/2; i += NT_) ((uint32_t*)sh_h2)[i] = 0u;
    if (tid < MB_) sh_i[tid] = (int)g_upk[m0 + tid];

#pragma unroll 1
    for (int t = 0; t < L_; t++) {
        const bool doH = (t > 0);
        float nn[2][4][4];
        {
            float rr[2][4][4];
            __syncthreads();
            if (doH) stage_pair(sh_B, g_W1h, g_W1l, 0, tid);
            __syncthreads();
            load_gi1(rr, 0, t, sh_i, sh_bh, 1, rbase, g, tg2, wc);
            if (doH) run_gemm(rr, sh_h2 + rbase*APITCH, sh_B, lane, wc);
#pragma unroll
            for (int mt=0; mt<2; mt++)
#pragma unroll
                for (int nt=0; nt<4; nt++)
#pragma unroll
                    for (int q=0; q<4; q++) rr[mt][nt][q] = sigf(rr[mt][nt][q]);

            __syncthreads();
            if (doH) stage_pair(sh_B, g_W1h, g_W1l, 2, tid);
            __syncthreads();
            float acci[2][4][4], acch[2][4][4];
            load_gi1(acci, 2, t, sh_i, nullptr, 0, rbase, g, tg2, wc);
#pragma unroll
            for (int mt=0; mt<2; mt++)
#pragma unroll
                for (int nt=0; nt<4; nt++) {
                    int cc = 2*F_ + wc*32 + nt*8 + tg2;
                    float2 bh = *(const float2*)&sh_bh[cc];
                    acch[mt][nt][0]=bh.x; acch[mt][nt][1]=bh.y;
                    acch[mt][nt][2]=bh.x; acch[mt][nt][3]=bh.y;
                }
            if (doH) run_gemm(acch, sh_h2 + rbase*APITCH, sh_B, lane, wc);
#pragma unroll
            for (int mt=0; mt<2; mt++)
#pragma unroll
                for (int nt=0; nt<4; nt++)
#pragma unroll
                    for (int q=0; q<4; q++)
                        nn[mt][nt][q] = tanh_s(acci[mt][nt][q] + rr[mt][nt][q]*acch[mt][nt][q]);
        }

        float zz[2][4][4];
        __syncthreads();
        if (doH) stage_pair(sh_B, g_W1h, g_W1l, 1, tid);
        __syncthreads();
        load_gi1(zz, 1, t, sh_i, sh_bh, 1, rbase, g, tg2, wc);
        if (doH) run_gemm(zz, sh_h2 + rbase*APITCH, sh_B, lane, wc);
#pragma unroll
        for (int mt=0; mt<2; mt++)
#pragma unroll
            for (int nt=0; nt<4; nt++)
#pragma unroll
                for (int q=0; q<4; q++) zz[mt][nt][q] = sigf(zz[mt][nt][q]);

        __syncthreads();
#pragma unroll
        for (int mt=0; mt<2; mt++)
#pragma unroll
            for (int nt=0; nt<4; nt++) {
                int cc = wc*32 + nt*8 + tg2;
#pragma unroll
                for (int p2=0; p2<2; p2++) {
                    int r = rbase + mt*16 + g + p2*8;
                    float n0 = nn[mt][nt][p2*2], n1 = nn[mt][nt][p2*2+1];
                    float z0 = zz[mt][nt][p2*2], z1 = zz[mt][nt][p2*2+1];
                    float2 hh = unpackbf(*(uint32_t*)&sh_h2[r*APITCH + cc]);
                    float2 hl = unpackbf(*(uint32_t*)&sh_h2[r*APITCH + 128 + cc]);
                    float h0 = (1.f - z0)*n0 + z0*(hh.x + hl.x);
                    float h1 = (1.f - z1)*n1 + z1*(hh.y + hl.y);
                    __nv_bfloat16 s0 = __float2bfloat16(h0), s1 = __float2bfloat16(h1);
                    __nv_bfloat162 hv; hv.x = s0; hv.y = s1;
                    uint32_t hiv = *(uint32_t*)&hv;
                    __nv_bfloat162 lv = __floats2bfloat162_rn(h0 - __bfloat162float(s0),
                                                              h1 - __bfloat162float(s1));
                    uint32_t lov = *(uint32_t*)&lv;
                    *(uint32_t*)&sh_h2[r*APITCH + cc] = hiv;
                    *(uint32_t*)&sh_h2[r*APITCH + 128 + cc] = lov;
                    size_t base = ((size_t)t*SEQ_ + m0 + r)*256 + cc;
                    *(uint32_t*)&g_yw2[base]       = hiv;
                    *(uint32_t*)&g_yw2[base + 128] = lov;
                }
            }
    }
}

// ---------------- GRU2 ----------------
__global__ void __launch_bounds__(NT_, 1) gru2_kernel(const float* __restrict__ bhh,
                                                      float* __restrict__ hT_out)
{
    extern __shared__ char smc[];
    __nv_bfloat16* sh_h2 = (__nv_bfloat16*)smc;                  // 33792
    __nv_bfloat16* sh_x2 = (__nv_bfloat16*)(smc + 33792);        // 33792
    __nv_bfloat16* sh_B  = (__nv_bfloat16*)(smc + 67584);        // 139264 (4 chunks)
    float* sh_bh = (float*)(smc + 67584 + 139264);               // 1536
    int*   sh_i  = (int*)(sh_bh + G3_);                          // 256

    const int tid = threadIdx.x, wid = tid >> 5, lane = tid & 31;
    const int wr = wid & 1, wc = wid >> 1;
    const int g = lane >> 2, tg2 = (lane & 3)*2;
    const int rbase = wr*32;
    const int m0 = blockIdx.x*MB_;
    const uint32_t sBu = (uint32_t)__cvta_generic_to_shared(sh_B);
    __nv_bfloat16* sh_BH = sh_B + 2*CHUNKE;

    for (int i = tid; i < G3_; i += NT_) sh_bh[i] = bhh[i];
#pragma unroll
    for (int it = 0; it < 8; it++) {
        int i = tid + it*NT_;
        int row = i >> 5, seg = (i & 31) << 3;
        *(uint4*)(sh_h2 + row*APITCH + seg) =
            *(const uint4*)(g_yw2 + ((size_t)(L_-1)*SEQ_ + m0 + row)*256 + seg);
    }

#pragma unroll 1
    for (int t = 0; t < L_; t++) {
        __syncthreads();
#pragma unroll
        for (int it = 0; it < 8; it++) {
            int i = tid + it*NT_;
            int row = i >> 5, seg = (i & 31) << 3;
            *(uint4*)(sh_x2 + row*APITCH + seg) =
                *(const uint4*)(g_yw2 + ((size_t)t*SEQ_ + m0 + row)*256 + seg);
        }
        if (tid < MB_) sh_i[tid] = g_walksf[(size_t)(m0 + tid)*L_ + t];
        stage_async(sBu, g_WXh, g_WXl, 0, tid);
        stage_async(sBu + 2u*CHUNKE*2u, g_W2h, g_W2l, 0, tid);
        __syncthreads();

        float nn[2][4][4];
        {
            // ---- gate r ----
            float rr[2][4][4];
            load_gi2(rr, 0, sh_i, sh_bh, 1, rbase, g, tg2, wc);
            cp_wait_all();
            __syncthreads();
            run_gemm(rr, sh_x2 + rbase*APITCH, sh_B, lane, wc);
            run_gemm(rr, sh_h2 + rbase*APITCH, sh_BH, lane, wc);
#pragma unroll
            for (int mt=0; mt<2; mt++)
#pragma unroll
                for (int nt=0; nt<4; nt++)
#pragma unroll
                    for (int q=0; q<4; q++) rr[mt][nt][q] = sigf(rr[mt][nt][q]);

            // ---- gate n ----
            __syncthreads();
            stage_async(sBu, g_WXh, g_WXl, 2, tid);
            stage_async(sBu + 2u*CHUNKE*2u, g_W2h, g_W2l, 2, tid);
            float acci[2][4][4], acch[2][4][4];
            load_gi2(acci, 2, sh_i, nullptr, 0, rbase, g, tg2, wc);
#pragma unroll
            for (int mt=0; mt<2; mt++)
#pragma unroll
                for (int nt=0; nt<4; nt++) {
                    int cc = 2*F_ + wc*32 + nt*8 + tg2;
                    float2 bh = *(const float2*)&sh_bh[cc];
                    acch[mt][nt][0]=bh.x; acch[mt][nt][1]=bh.y;
                    acch[mt][nt][2]=bh.x; acch[mt][nt][3]=bh.y;
                }
            cp_wait_all();
            __syncthreads();
            run_gemm(acci, sh_x2 + rbase*APITCH, sh_B, lane, wc);
            run_gemm(acch, sh_h2 + rbase*APITCH, sh_BH, lane, wc);
#pragma unroll
            for (int mt=0; mt<2; mt++)
#pragma unroll
                for (int nt=0; nt<4; nt++)
#pragma unroll
                    for (int q=0; q<4; q++)
                        nn[mt][nt][q] = tanh_s(acci[mt][nt][q] + rr[mt][nt][q]*acch[mt][nt][q]);
        }

        // ---- gate z ----
        float zz[2][4][4];
        __syncthreads();
        stage_async(sBu, g_WXh, g_WXl, 1, tid);
        stage_async(sBu + 2u*CHUNKE*2u, g_W2h, g_W2l, 1, tid);
        load_gi2(zz, 1, sh_i, sh_bh, 1, rbase, g, tg2, wc);
        cp_wait_all();
        __syncthreads();
        run_gemm(zz, sh_x2 + rbase*APITCH, sh_B, lane, wc);
        run_gemm(zz, sh_h2 + rbase*APITCH, sh_BH, lane, wc);
#pragma unroll
        for (int mt=0; mt<2; mt++)
#pragma unroll
            for (int nt=0; nt<4; nt++)
#pragma unroll
                for (int q=0; q<4; q++) zz[mt][nt][q] = sigf(zz[mt][nt][q]);

        __syncthreads();
#pragma unroll
        for (int mt=0; mt<2; mt++)
#pragma unroll
            for (int nt=0; nt<4; nt++) {
                int cc = wc*32 + nt*8 + tg2;
#pragma unroll
                for (int p2=0; p2<2; p2++) {
                    int r = rbase + mt*16 + g + p2*8;
                    float n0 = nn[mt][nt][p2*2], n1 = nn[mt][nt][p2*2+1];
                    float z0 = zz[mt][nt][p2*2], z1 = zz[mt][nt][p2*2+1];
                    float2 hh = unpackbf(*(uint32_t*)&sh_h2[r*APITCH + cc]);
                    float2 hl = unpackbf(*(uint32_t*)&sh_h2[r*APITCH + 128 + cc]);
                    float h0 = (1.f - z0)*n0 + z0*(hh.x + hl.x);
                    float h1 = (1.f - z1)*n1 + z1*(hh.y + hl.y);
                    __nv_bfloat16 s0 = __float2bfloat16(h0), s1 = __float2bfloat16(h1);
                    __nv_bfloat162 hv; hv.x = s0; hv.y = s1;
                    uint32_t hiv = *(uint32_t*)&hv;
                    __nv_bfloat162 lv = __floats2bfloat162_rn(h0 - __bfloat162float(s0),
                                                              h1 - __bfloat162float(s1));
                    uint32_t lov = *(uint32_t*)&lv;
                    *(uint32_t*)&sh_h2[r*APITCH + cc] = hiv;
                    *(uint32_t*)&sh_h2[r*APITCH + 128 + cc] = lov;
                    float* dst = (t < L_-1) ? (g_yseq[t] + ((size_t)(m0+r))*F_ + cc)
                                            : (hT_out   + ((size_t)(m0+r))*F_ + cc);
                    *(float2*)dst = make_float2(h0, h1);
                }
            }
    }
}

// ---------------- loss ----------------
__global__ void lsum_kernel(const int* __restrict__ idxs, const float* __restrict__ y0)
{
    int b = blockIdx.x;
    int t = b % (L_-1), j = (b/(L_-1)) % SUB_, s = b/((L_-1)*SUB_);
    int seq = s*N_ + idxs[j];
    int node = g_walksf[(size_t)seq*L_ + t + 1];
    int o = threadIdx.x;
    __shared__ float red[OR_];
    red[o] = y0[(size_t)node*OR_ + o]; __syncthreads();
    for (int st = OR_/2; st > 0; st >>= 1) { if (o < st) red[o] += red[o+st]; __syncthreads(); }
    if (o == 0) g_part1[b] = red[0];
}

__global__ void lred1_kernel()
{
    __shared__ float red[256];
    int tid = threadIdx.x; float s = 0.f;
    for (int i = tid; i < NB_LOSS; i += 256) s += g_part1[i];
    red[tid] = s; __syncthreads();
    for (int st = 128; st > 0; st >>= 1) { if (tid < st) red[tid] += red[tid+st]; __syncthreads(); }
    if (tid == 0) g_posw = LOSS_CNT / red[0];
}

__global__ void lbce_kernel(const int* __restrict__ idxs, const float* __restrict__ y0,
                            const float* __restrict__ Wss, const float* __restrict__ bss)
{
    int b = blockIdx.x;
    int t = b % (L_-1), j = (b/(L_-1)) % SUB_, s = b/((L_-1)*SUB_);
    int seq = s*N_ + idxs[j];
    __shared__ float yrow[F_];
    int o = threadIdx.x;
    yrow[o]      = g_yseq[t][(size_t)seq*F_ + o];
    yrow[o + 64] = g_yseq[t][(size_t)seq*F_ + o + 64];
    __syncthreads();
    float acc = bss[o];
    const float4* wrp = (const float4*)(Wss + (size_t)o*F_);
#pragma unroll 8
    for (int k = 0; k < F_/4; k++) {
        float4 w = wrp[k];
        acc += yrow[k*4]*w.x + yrow[k*4+1]*w.y + yrow[k*4+2]*w.z + yrow[k*4+3]*w.w;
    }
    int node = g_walksf[(size_t)seq*L_ + t + 1];
    float yt = y0[(size_t)node*OR_ + o];
    float term = g_posw * yt * softplusf(-acc) + (1.f - yt) * softplusf(acc);
    __shared__ float red[OR_];
    red[o] = term; __syncthreads();
    for (int st = OR_/2; st > 0; st >>= 1) { if (o < st) red[o] += red[o+st]; __syncthreads(); }
    if (o == 0) g_part2[b] = red[0];
}

__global__ void lred2_kernel(float* __restrict__ dst)
{
    __shared__ float red[256];
    int tid = threadIdx.x; float s = 0.f;
    for (int i = tid; i < NB_LOSS; i += 256) s += g_part2[i];
    red[tid] = s; __syncthreads();
    for (int st = 128; st > 0; st >>= 1) { if (tid < st) red[tid] += red[tid+st]; __syncthreads(); }
    if (tid == 0) *dst = red[0] / LOSS_CNT;
}

// ---------------- launch ----------------
extern "C" void kernel_launch(void* const* d_in, const int* in_sizes, int n_in,
                              void* d_out, int out_size)
{
    const float* h     = (const float*)d_in[0];
    const float* y0    = (const float*)d_in[1];
    const float* Wih_w = (const float*)d_in[2];
    const float* Whh_w = (const float*)d_in[3];
    const float* bih_w = (const float*)d_in[4];
    const float* bhh_w = (const float*)d_in[5];
    const float* Wih   = (const float*)d_in[6];
    const float* Whh   = (const float*)d_in[7];
    const float* bih   = (const float*)d_in[8];
    const float* bhh   = (const float*)d_in[9];
    const float* W_ss  = (const float*)d_in[10];
    const float* b_ss  = (const float*)d_in[11];
    const int*   walks = (const int*)d_in[12];
    const int*   idxs  = (const int*)d_in[13];
    float* out = (float*)d_out;

    const int SMEM_P  = (MB_*132 + 32*128) * 4;             // 50176
    const int SMEM_G1 = 33792 + 69632 + G3_*4 + 256;        // 105216
    const int SMEM_G2 = 33792*2 + 4*CHUNKE*2 + G3_*4 + 256; // 208640
    cudaFuncSetAttribute(p_kernel,    cudaFuncAttributeMaxDynamicSharedMemorySize, SMEM_P);
    cudaFuncSetAttribute(gru1_kernel, cudaFuncAttributeMaxDynamicSharedMemorySize, SMEM_G1);
    cudaFuncSetAttribute(gru2_kernel, cudaFuncAttributeMaxDynamicSharedMemorySize, SMEM_G2);

    prep_kernel<<<(SEQ_ + 255)/256, 256>>>(walks);
    wg_kernel<<<1, G3_>>>(Wih_w, bih_w);
    pack_kernel<<<(G3_*F_ + 255)/256, 256>>>(Whh_w, Whh, Wih);
    p_kernel<<<dim3((N_ + MB_-1)/MB_, 3), NT_, SMEM_P>>>(h, Wih, bih);
    gru1_kernel<<<TILES_, NT_, SMEM_G1>>>(bhh_w);
    gru2_kernel<<<TILES_, NT_, SMEM_G2>>>(bhh, out);
    lsum_kernel<<<NB_LOSS, OR_>>>(idxs, y0);
    lred1_kernel<<<1, 256>>>();
    lbce_kernel<<<NB_LOSS, OR_>>>(idxs, y0, W_ss, b_ss);
    lred2_kernel<<<1, 256>>>(out + (out_size - 1));
}

// round 10
// speedup vs baseline: 1.5179x; 1.0104x over previous
#include <cuda_runtime.h>
#include <cuda_bf16.h>
#include <math.h>
#include <stdint.h>

#define S_    4
#define N_    10000
#define NP_   10048                // padded rows for pT
#define L_    8
#define F_    128
#define G3_   384
#define OR_   64
#define SUB_  100
#define SEQ_  (S_*N_)
#define MB_   64
#define NT_   256
#define TILES_ (SEQ_/MB_)          // 625
#define PTILES_ (NP_/MB_)          // 157
#define NB_LOSS (S_*SUB_*(L_-1))
#define LOSS_CNT 179200.0f
#define APITCH 264
#define BPITCH 136
#define CHUNKE (128*BPITCH)

__device__ int      g_walksf[SEQ_*L_];
__device__ unsigned g_upk[SEQ_];
__device__ float    g_wg[8*G3_];
__device__ float    g_P[N_*G3_];
__device__ __nv_bfloat16 g_h2[(size_t)NP_*256];        // h split (hi|lo)
__device__ __nv_bfloat16 g_yw2[(size_t)L_*SEQ_*256];   // GRU1 out split (hi|lo)
__device__ float    g_yseq[L_-1][SEQ_*F_];
__device__ float    g_part1[NB_LOSS];
__device__ float    g_part2[NB_LOSS];
__device__ float    g_posw;
__device__ __nv_bfloat16 g_W1h[G3_*F_], g_W1l[G3_*F_];  // Whh_w split
__device__ __nv_bfloat16 g_W2h[G3_*F_], g_W2l[G3_*F_];  // Whh split
__device__ __nv_bfloat16 g_WXh[G3_*F_], g_WXl[G3_*F_];  // Wih[:,128:256] split
__device__ __nv_bfloat16 g_WAh[G3_*F_], g_WAl[G3_*F_];  // Wih[:,0:128] split

__device__ __forceinline__ float sigf(float x) { return __fdividef(1.f, 1.f + __expf(-x)); }
__device__ __forceinline__ float tanh_s(float x) {
    float ax = fabsf(x); float e = __expf(-2.f*ax);
    return copysignf(__fdividef(1.f - e, 1.f + e), x);
}
__device__ __forceinline__ float softplusf(float x) {
    return fmaxf(x, 0.f) + log1pf(__expf(-fabsf(x)));
}
__device__ __forceinline__ float2 unpackbf(uint32_t u) {
    __nv_bfloat162 v = *(__nv_bfloat162*)&u;
    return make_float2(__bfloat162float(v.x), __bfloat162float(v.y));
}

__device__ __forceinline__ void mma16816(float c[4], uint32_t a0, uint32_t a1,
                                         uint32_t a2, uint32_t a3, uint32_t b0, uint32_t b1) {
    asm volatile("mma.sync.aligned.m16n8k16.row.col.f32.bf16.bf16.f32 "
                 "{%0,%1,%2,%3}, {%4,%5,%6,%7}, {%8,%9}, {%0,%1,%2,%3};\n"
                 : "+f"(c[0]), "+f"(c[1]), "+f"(c[2]), "+f"(c[3])
                 : "r"(a0), "r"(a1), "r"(a2), "r"(a3), "r"(b0), "r"(b1));
}
__device__ __forceinline__ void ldsm_x4(uint32_t& r0, uint32_t& r1, uint32_t& r2, uint32_t& r3,
                                        const void* p) {
    uint32_t a = (uint32_t)__cvta_generic_to_shared(p);
    asm volatile("ldmatrix.sync.aligned.m8n8.x4.shared.b16 {%0,%1,%2,%3}, [%4];"
                 : "=r"(r0), "=r"(r1), "=r"(r2), "=r"(r3) : "r"(a));
}

// 3-segment pair GEMM (GRU1): Whi at B, Wlo at B+CHUNKE
__device__ __forceinline__ void run_gemm(float (&acc)[2][4][4],
    const __nv_bfloat16* __restrict__ A, const __nv_bfloat16* __restrict__ B,
    int lane, int wc)
{
    const int rl = lane & 15;
    const int kp = (lane >> 4) << 3;
#pragma unroll
    for (int ks = 0; ks < 8; ks++) {
        const int k0 = ks*16 + kp;
        uint32_t ah[2][4], al[2][4];
#pragma unroll
        for (int mt = 0; mt < 2; mt++) {
            const __nv_bfloat16* Ar = A + (mt*16 + rl)*APITCH + k0;
            ldsm_x4(ah[mt][0], ah[mt][1], ah[mt][2], ah[mt][3], Ar);
            ldsm_x4(al[mt][0], al[mt][1], al[mt][2], al[mt][3], Ar + 128);
        }
#pragma unroll
        for (int np = 0; np < 2; np++) {
            const __nv_bfloat16* Br = B + (wc*32 + np*16 + rl)*BPITCH + k0;
            uint32_t bh[4], bl[4];
            ldsm_x4(bh[0], bh[1], bh[2], bh[3], Br);
            ldsm_x4(bl[0], bl[1], bl[2], bl[3], Br + CHUNKE);
#pragma unroll
            for (int mt = 0; mt < 2; mt++) {
                mma16816(acc[mt][np*2+0], ah[mt][0], ah[mt][1], ah[mt][2], ah[mt][3], bh[0], bh[2]);
                mma16816(acc[mt][np*2+1], ah[mt][0], ah[mt][1], ah[mt][2], ah[mt][3], bh[1], bh[3]);
                mma16816(acc[mt][np*2+0], al[mt][0], al[mt][1], al[mt][2], al[mt][3], bh[0], bh[2]);
                mma16816(acc[mt][np*2+1], al[mt][0], al[mt][1], al[mt][2], al[mt][3], bh[1], bh[3]);
                mma16816(acc[mt][np*2+0], ah[mt][0], ah[mt][1], ah[mt][2], ah[mt][3], bl[0], bl[2]);
                mma16816(acc[mt][np*2+1], ah[mt][0], ah[mt][1], ah[mt][2], ah[mt][3], bl[1], bl[3]);
            }
        }
    }
}

// single-chunk GEMMs (GRU2/pT): run2 = (Ahi+Alo)*W, run1 = Ahi*W
template<int WITH_LO>
__device__ __forceinline__ void run_seg(float (&acc)[2][4][4],
    const __nv_bfloat16* __restrict__ A, const __nv_bfloat16* __restrict__ W,
    int lane, int wc)
{
    const int rl = lane & 15;
    const int kp = (lane >> 4) << 3;
#pragma unroll
    for (int ks = 0; ks < 8; ks++) {
        const int k0 = ks*16 + kp;
        uint32_t ah[2][4], al[2][4];
#pragma unroll
        for (int mt = 0; mt < 2; mt++) {
            const __nv_bfloat16* Ar = A + (mt*16 + rl)*APITCH + k0;
            ldsm_x4(ah[mt][0], ah[mt][1], ah[mt][2], ah[mt][3], Ar);
            if (WITH_LO) ldsm_x4(al[mt][0], al[mt][1], al[mt][2], al[mt][3], Ar + 128);
        }
#pragma unroll
        for (int np = 0; np < 2; np++) {
            const __nv_bfloat16* Wr = W + (wc*32 + np*16 + rl)*BPITCH + k0;
            uint32_t bh[4];
            ldsm_x4(bh[0], bh[1], bh[2], bh[3], Wr);
#pragma unroll
            for (int mt = 0; mt < 2; mt++) {
                mma16816(acc[mt][np*2+0], ah[mt][0], ah[mt][1], ah[mt][2], ah[mt][3], bh[0], bh[2]);
                mma16816(acc[mt][np*2+1], ah[mt][0], ah[mt][1], ah[mt][2], ah[mt][3], bh[1], bh[3]);
                if (WITH_LO) {
                    mma16816(acc[mt][np*2+0], al[mt][0], al[mt][1], al[mt][2], al[mt][3], bh[0], bh[2]);
                    mma16816(acc[mt][np*2+1], al[mt][0], al[mt][1], al[mt][2], al[mt][3], bh[1], bh[3]);
                }
            }
        }
    }
}

// sync pair staging (GRU1)
__device__ __forceinline__ void stage_pair(__nv_bfloat16* dst,
    const __nv_bfloat16* __restrict__ hi, const __nv_bfloat16* __restrict__ lo,
    int jg, int tid)
{
    const __nv_bfloat16* s0 = hi + (size_t)jg*128*128;
    const __nv_bfloat16* s1 = lo + (size_t)jg*128*128;
#pragma unroll
    for (int it = 0; it < 8; it++) {
        int i = tid + it*NT_;
        int row = i >> 4, seg = (i & 15) << 3;
        *(uint4*)(dst + row*BPITCH + seg)          = *(const uint4*)(s0 + row*128 + seg);
        *(uint4*)(dst + CHUNKE + row*BPITCH + seg) = *(const uint4*)(s1 + row*128 + seg);
    }
}

// async single-chunk staging (GRU2/pT)
__device__ __forceinline__ void cpa16(uint32_t d, const void* s) {
    asm volatile("cp.async.cg.shared.global [%0], [%1], 16;\n" :: "r"(d), "l"(s));
}
__device__ __forceinline__ void stage1(uint32_t dstB, const __nv_bfloat16* __restrict__ src,
                                       int tid)
{
#pragma unroll
    for (int it = 0; it < 8; it++) {
        int i = tid + it*NT_;
        int row = i >> 4, seg = (i & 15) << 3;
        cpa16(dstB + (uint32_t)(row*BPITCH + seg)*2u, src + row*128 + seg);
    }
}
__device__ __forceinline__ void cp_wait_all() {
    asm volatile("cp.async.commit_group;\n");
    asm volatile("cp.async.wait_group 0;\n" ::: "memory");
}

// GRU1 gi loader (wg table in global)
__device__ __forceinline__ void load_gi1(float (&acc)[2][4][4], int jg, int t,
    const int* __restrict__ sh_i, const float* __restrict__ sh_bh, int addbias,
    int rbase, int g, int tg2, int wc)
{
#pragma unroll
    for (int mt = 0; mt < 2; mt++) {
        int u0 = (sh_i[rbase + mt*16 + g]     >> (4*t)) & 7;
        int u1 = (sh_i[rbase + mt*16 + g + 8] >> (4*t)) & 7;
#pragma unroll
        for (int nt = 0; nt < 4; nt++) {
            int cc = jg*F_ + wc*32 + nt*8 + tg2;
            float2 p0 = *(const float2*)&g_wg[u0*G3_ + cc];
            float2 p1 = *(const float2*)&g_wg[u1*G3_ + cc];
            acc[mt][nt][0]=p0.x; acc[mt][nt][1]=p0.y; acc[mt][nt][2]=p1.x; acc[mt][nt][3]=p1.y;
            if (addbias) {
                float2 bh = *(const float2*)&sh_bh[cc];
                acc[mt][nt][0]+=bh.x; acc[mt][nt][1]+=bh.y; acc[mt][nt][2]+=bh.x; acc[mt][nt][3]+=bh.y;
            }
        }
    }
}

// GRU2 gi loader (P gather)
__device__ __forceinline__ void load_gi2(float (&acc)[2][4][4], int jg,
    const int* __restrict__ sh_i, const float* __restrict__ sh_bh, int addbias,
    int rbase, int g, int tg2, int wc)
{
#pragma unroll
    for (int mt = 0; mt < 2; mt++) {
        int i0 = sh_i[rbase + mt*16 + g], i1 = sh_i[rbase + mt*16 + g + 8];
#pragma unroll
        for (int nt = 0; nt < 4; nt++) {
            int cc = jg*F_ + wc*32 + nt*8 + tg2;
            float2 p0 = *(const float2*)&g_P[(size_t)i0*G3_ + cc];
            float2 p1 = *(const float2*)&g_P[(size_t)i1*G3_ + cc];
            acc[mt][nt][0]=p0.x; acc[mt][nt][1]=p0.y; acc[mt][nt][2]=p1.x; acc[mt][nt][3]=p1.y;
            if (addbias) {
                float2 bh = *(const float2*)&sh_bh[cc];
                acc[mt][nt][0]+=bh.x; acc[mt][nt][1]+=bh.y; acc[mt][nt][2]+=bh.x; acc[mt][nt][3]+=bh.y;
            }
        }
    }
}

// ---------------- preprocessing ----------------
__global__ void prep_kernel(const int* __restrict__ walks)
{
    int m = blockIdx.x * blockDim.x + threadIdx.x;
    if (m >= SEQ_) return;
    int w[L_];
#pragma unroll
    for (int p = 0; p < L_; p++) w[p] = walks[m*L_ + p];
    unsigned pk = 0;
#pragma unroll
    for (int t = 0; t < L_; t++) {
        int p = L_-1-t, wp = w[p], u = p;
#pragma unroll
        for (int q = L_-1; q >= 0; q--) if (w[q] == wp) u = q;
        g_walksf[m*L_ + t] = wp;
        pk |= ((unsigned)u) << (4*t);
    }
    g_upk[m] = pk;
}

__global__ void wg_kernel(const float* __restrict__ Wih_w, const float* __restrict__ bih_w)
{
    int j = threadIdx.x;
    float b = bih_w[j];
#pragma unroll
    for (int u = 0; u < 8; u++) g_wg[u*G3_ + j] = Wih_w[j*8 + u] + b;
}

__global__ void pack_kernel(const float* __restrict__ Whh_w, const float* __restrict__ Whh,
                            const float* __restrict__ Wih)
{
    int i = blockIdx.x * 256 + threadIdx.x;
    if (i >= G3_*F_) return;
    float a = Whh_w[i];
    __nv_bfloat16 h1 = __float2bfloat16(a);
    g_W1h[i] = h1; g_W1l[i] = __float2bfloat16(a - __bfloat162float(h1));
    float b = Whh[i];
    __nv_bfloat16 h2 = __float2bfloat16(b);
    g_W2h[i] = h2; g_W2l[i] = __float2bfloat16(b - __bfloat162float(h2));
    int n = i >> 7, k = i & 127;
    float c = Wih[n*256 + 128 + k];
    __nv_bfloat16 h3 = __float2bfloat16(c);
    g_WXh[i] = h3; g_WXl[i] = __float2bfloat16(c - __bfloat162float(h3));
    float d = Wih[n*256 + k];
    __nv_bfloat16 h4 = __float2bfloat16(d);
    g_WAh[i] = h4; g_WAl[i] = __float2bfloat16(d - __bfloat162float(h4));
}

__global__ void packh_kernel(const float* __restrict__ h)
{
    int i = blockIdx.x * 256 + threadIdx.x;
    if (i >= NP_*F_) return;
    int n = i >> 7, k = i & 127;
    float v = (n < N_) ? h[(size_t)n*F_ + k] : 0.f;
    __nv_bfloat16 hi = __float2bfloat16(v);
    g_h2[(size_t)n*256 + k]       = hi;
    g_h2[(size_t)n*256 + 128 + k] = __float2bfloat16(v - __bfloat162float(hi));
}

// ---------------- P = h @ WihA^T + bih (tensor cores) ----------------
__global__ void __launch_bounds__(NT_) pT_kernel(const float* __restrict__ bih)
{
    extern __shared__ char smc[];
    __nv_bfloat16* sh_x2 = (__nv_bfloat16*)smc;            // 33792
    __nv_bfloat16* sh_W  = (__nv_bfloat16*)(smc + 33792);  // 34816

    const int tid = threadIdx.x, wid = tid >> 5, lane = tid & 31;
    const int wr = wid & 1, wc = wid >> 1;
    const int g = lane >> 2, tg2 = (lane & 3)*2;
    const int rbase = wr*32;
    const int m0 = blockIdx.x*MB_, jg = blockIdx.y;
    const uint32_t sWu = (uint32_t)__cvta_generic_to_shared(sh_W);

#pragma unroll
    for (int it = 0; it < 8; it++) {
        int i = tid + it*NT_;
        int row = i >> 5, seg = (i & 31) << 3;
        *(uint4*)(sh_x2 + row*APITCH + seg) =
            *(const uint4*)(g_h2 + ((size_t)(m0 + row))*256 + seg);
    }
    stage1(sWu, g_WAh + (size_t)jg*16384, tid);
    cp_wait_all();
    __syncthreads();

    float acc[2][4][4];
#pragma unroll
    for (int mt = 0; mt < 2; mt++)
#pragma unroll
        for (int nt = 0; nt < 4; nt++) {
            int cc = jg*F_ + wc*32 + nt*8 + tg2;
            float2 b = *(const float2*)&bih[cc];
            acc[mt][nt][0]=b.x; acc[mt][nt][1]=b.y; acc[mt][nt][2]=b.x; acc[mt][nt][3]=b.y;
        }
    run_seg<1>(acc, sh_x2 + rbase*APITCH, sh_W, lane, wc);
    __syncthreads();
    stage1(sWu, g_WAl + (size_t)jg*16384, tid);
    cp_wait_all();
    __syncthreads();
    run_seg<0>(acc, sh_x2 + rbase*APITCH, sh_W, lane, wc);

#pragma unroll
    for (int mt = 0; mt < 2; mt++)
#pragma unroll
        for (int nt = 0; nt < 4; nt++) {
            int cc = jg*F_ + wc*32 + nt*8 + tg2;
#pragma unroll
            for (int p2 = 0; p2 < 2; p2++) {
                int n = m0 + rbase + mt*16 + g + p2*8;
                if (n < N_)
                    *(float2*)&g_P[(size_t)n*G3_ + cc] =
                        make_float2(acc[mt][nt][p2*2], acc[mt][nt][p2*2+1]);
            }
        }
}

// ---------------- GRU1 (round-7, 2 blocks/SM) ----------------
__global__ void __launch_bounds__(NT_, 2) gru1_kernel(const float* __restrict__ bhh)
{
    extern __shared__ char smc[];
    __nv_bfloat16* sh_h2 = (__nv_bfloat16*)smc;                  // 33792
    __nv_bfloat16* sh_B  = (__nv_bfloat16*)(smc + 33792);        // 69632
    float* sh_bh = (float*)(smc + 33792 + 69632);
    int*   sh_i  = (int*)(sh_bh + G3_);

    const int tid = threadIdx.x, wid = tid >> 5, lane = tid & 31;
    const int wr = wid & 1, wc = wid >> 1;
    const int g = lane >> 2, tg2 = (lane & 3)*2;
    const int rbase = wr*32;
    const int m0 = blockIdx.x*MB_;

    for (int i = tid; i < G3_; i += NT_) sh_bh[i] = bhh[i];
    for (int i = tid; i < MB_*APITCH/2; i += NT_) ((uint32_t*)sh_h2)[i] = 0u;
    if (tid < MB_) sh_i[tid] = (int)g_upk[m0 + tid];

#pragma unroll 1
    for (int t = 0; t < L_; t++) {
        const bool doH = (t > 0);
        float nn[2][4][4];
        {
            float rr[2][4][4];
            __syncthreads();
            if (doH) stage_pair(sh_B, g_W1h, g_W1l, 0, tid);
            __syncthreads();
            load_gi1(rr, 0, t, sh_i, sh_bh, 1, rbase, g, tg2, wc);
            if (doH) run_gemm(rr, sh_h2 + rbase*APITCH, sh_B, lane, wc);
#pragma unroll
            for (int mt=0; mt<2; mt++)
#pragma unroll
                for (int nt=0; nt<4; nt++)
#pragma unroll
                    for (int q=0; q<4; q++) rr[mt][nt][q] = sigf(rr[mt][nt][q]);

            __syncthreads();
            if (doH) stage_pair(sh_B, g_W1h, g_W1l, 2, tid);
            __syncthreads();
            float acci[2][4][4], acch[2][4][4];
            load_gi1(acci, 2, t, sh_i, nullptr, 0, rbase, g, tg2, wc);
#pragma unroll
            for (int mt=0; mt<2; mt++)
#pragma unroll
                for (int nt=0; nt<4; nt++) {
                    int cc = 2*F_ + wc*32 + nt*8 + tg2;
                    float2 bh = *(const float2*)&sh_bh[cc];
                    acch[mt][nt][0]=bh.x; acch[mt][nt][1]=bh.y;
                    acch[mt][nt][2]=bh.x; acch[mt][nt][3]=bh.y;
                }
            if (doH) run_gemm(acch, sh_h2 + rbase*APITCH, sh_B, lane, wc);
#pragma unroll
            for (int mt=0; mt<2; mt++)
#pragma unroll
                for (int nt=0; nt<4; nt++)
#pragma unroll
                    for (int q=0; q<4; q++)
                        nn[mt][nt][q] = tanh_s(acci[mt][nt][q] + rr[mt][nt][q]*acch[mt][nt][q]);
        }

        float zz[2][4][4];
        __syncthreads();
        if (doH) stage_pair(sh_B, g_W1h, g_W1l, 1, tid);
        __syncthreads();
        load_gi1(zz, 1, t, sh_i, sh_bh, 1, rbase, g, tg2, wc);
        if (doH) run_gemm(zz, sh_h2 + rbase*APITCH, sh_B, lane, wc);
#pragma unroll
        for (int mt=0; mt<2; mt++)
#pragma unroll
            for (int nt=0; nt<4; nt++)
#pragma unroll
                for (int q=0; q<4; q++) zz[mt][nt][q] = sigf(zz[mt][nt][q]);

        __syncthreads();
#pragma unroll
        for (int mt=0; mt<2; mt++)
#pragma unroll
            for (int nt=0; nt<4; nt++) {
                int cc = wc*32 + nt*8 + tg2;
#pragma unroll
                for (int p2=0; p2<2; p2++) {
                    int r = rbase + mt*16 + g + p2*8;
                    float n0 = nn[mt][nt][p2*2], n1 = nn[mt][nt][p2*2+1];
                    float z0 = zz[mt][nt][p2*2], z1 = zz[mt][nt][p2*2+1];
                    float2 hh = unpackbf(*(uint32_t*)&sh_h2[r*APITCH + cc]);
                    float2 hl = unpackbf(*(uint32_t*)&sh_h2[r*APITCH + 128 + cc]);
                    float h0 = (1.f - z0)*n0 + z0*(hh.x + hl.x);
                    float h1 = (1.f - z1)*n1 + z1*(hh.y + hl.y);
                    __nv_bfloat16 s0 = __float2bfloat16(h0), s1 = __float2bfloat16(h1);
                    __nv_bfloat162 hv; hv.x = s0; hv.y = s1;
                    uint32_t hiv = *(uint32_t*)&hv;
                    __nv_bfloat162 lv = __floats2bfloat162_rn(h0 - __bfloat162float(s0),
                                                              h1 - __bfloat162float(s1));
                    uint32_t lov = *(uint32_t*)&lv;
                    *(uint32_t*)&sh_h2[r*APITCH + cc] = hiv;
                    *(uint32_t*)&sh_h2[r*APITCH + 128 + cc] = lov;
                    size_t base = ((size_t)t*SEQ_ + m0 + r)*256 + cc;
                    *(uint32_t*)&g_yw2[base]       = hiv;
                    *(uint32_t*)&g_yw2[base + 128] = lov;
                }
            }
    }
}

// ---------------- GRU2: single-chunk staging, 2 blocks/SM ----------------
__device__ __forceinline__ void gate_gemm(float (&ax)[2][4][4], float (&ah2)[2][4][4], int jg,
    const __nv_bfloat16* sh_x2, const __nv_bfloat16* sh_h2, uint32_t sWu,
    const __nv_bfloat16* sh_W, int tid, int lane, int wc, int rbase)
{
    stage1(sWu, g_WXh + (size_t)jg*16384, tid);
    cp_wait_all(); __syncthreads();
    run_seg<1>(ax, sh_x2 + rbase*APITCH, sh_W, lane, wc);
    __syncthreads();
    stage1(sWu, g_WXl + (size_t)jg*16384, tid);
    cp_wait_all(); __syncthreads();
    run_seg<0>(ax, sh_x2 + rbase*APITCH, sh_W, lane, wc);
    __syncthreads();
    stage1(sWu, g_W2h + (size_t)jg*16384, tid);
    cp_wait_all(); __syncthreads();
    run_seg<1>(ah2, sh_h2 + rbase*APITCH, sh_W, lane, wc);
    __syncthreads();
    stage1(sWu, g_W2l + (size_t)jg*16384, tid);
    cp_wait_all(); __syncthreads();
    run_seg<0>(ah2, sh_h2 + rbase*APITCH, sh_W, lane, wc);
}

__global__ void __launch_bounds__(NT_, 2) gru2_kernel(const float* __restrict__ bhh,
                                                      float* __restrict__ hT_out)
{
    extern __shared__ char smc[];
    __nv_bfloat16* sh_h2 = (__nv_bfloat16*)smc;                  // 33792
    __nv_bfloat16* sh_x2 = (__nv_bfloat16*)(smc + 33792);        // 33792
    __nv_bfloat16* sh_W  = (__nv_bfloat16*)(smc + 67584);        // 34816
    float* sh_bh = (float*)(smc + 102400);                       // 1536
    int*   sh_i  = (int*)(smc + 103936);                         // 256

    const int tid = threadIdx.x, wid = tid >> 5, lane = tid & 31;
    const int wr = wid & 1, wc = wid >> 1;
    const int g = lane >> 2, tg2 = (lane & 3)*2;
    const int rbase = wr*32;
    const int m0 = blockIdx.x*MB_;
    const uint32_t sWu = (uint32_t)__cvta_generic_to_shared(sh_W);

    for (int i = tid; i < G3_; i += NT_) sh_bh[i] = bhh[i];
#pragma unroll
    for (int it = 0; it < 8; it++) {
        int i = tid + it*NT_;
        int row = i >> 5, seg = (i & 31) << 3;
        *(uint4*)(sh_h2 + row*APITCH + seg) =
            *(const uint4*)(g_yw2 + ((size_t)(L_-1)*SEQ_ + m0 + row)*256 + seg);
    }

#pragma unroll 1
    for (int t = 0; t < L_; t++) {
        __syncthreads();   // prior reads of sh_x2/sh_W done; epilogue writes of sh_h2 done
#pragma unroll
        for (int it = 0; it < 8; it++) {
            int i = tid + it*NT_;
            int row = i >> 5, seg = (i & 31) << 3;
            *(uint4*)(sh_x2 + row*APITCH + seg) =
                *(const uint4*)(g_yw2 + ((size_t)t*SEQ_ + m0 + row)*256 + seg);
        }
        if (tid < MB_) sh_i[tid] = g_walksf[(size_t)(m0 + tid)*L_ + t];
        __syncthreads();   // FIX: sh_i/sh_x2 visible to ALL threads before load_gi2

        float nn[2][4][4];
        {
            // ---- gate r ----
            float rr[2][4][4];
            load_gi2(rr, 0, sh_i, sh_bh, 1, rbase, g, tg2, wc);
            gate_gemm(rr, rr, 0, sh_x2, sh_h2, sWu, sh_W, tid, lane, wc, rbase);
#pragma unroll
            for (int mt=0; mt<2; mt++)
#pragma unroll
                for (int nt=0; nt<4; nt++)
#pragma unroll
                    for (int q=0; q<4; q++) rr[mt][nt][q] = sigf(rr[mt][nt][q]);

            // ---- gate n ----
            __syncthreads();
            float acci[2][4][4], acch[2][4][4];
            load_gi2(acci, 2, sh_i, nullptr, 0, rbase, g, tg2, wc);
#pragma unroll
            for (int mt=0; mt<2; mt++)
#pragma unroll
                for (int nt=0; nt<4; nt++) {
                    int cc = 2*F_ + wc*32 + nt*8 + tg2;
                    float2 bh = *(const float2*)&sh_bh[cc];
                    acch[mt][nt][0]=bh.x; acch[mt][nt][1]=bh.y;
                    acch[mt][nt][2]=bh.x; acch[mt][nt][3]=bh.y;
                }
            gate_gemm(acci, acch, 2, sh_x2, sh_h2, sWu, sh_W, tid, lane, wc, rbase);
#pragma unroll
            for (int mt=0; mt<2; mt++)
#pragma unroll
                for (int nt=0; nt<4; nt++)
#pragma unroll
                    for (int q=0; q<4; q++)
                        nn[mt][nt][q] = tanh_s(acci[mt][nt][q] + rr[mt][nt][q]*acch[mt][nt][q]);
        }

        // ---- gate z ----
        float zz[2][4][4];
        __syncthreads();
        load_gi2(zz, 1, sh_i, sh_bh, 1, rbase, g, tg2, wc);
        gate_gemm(zz, zz, 1, sh_x2, sh_h2, sWu, sh_W, tid, lane, wc, rbase);
#pragma unroll
        for (int mt=0; mt<2; mt++)
#pragma unroll
            for (int nt=0; nt<4; nt++)
#pragma unroll
                for (int q=0; q<4; q++) zz[mt][nt][q] = sigf(zz[mt][nt][q]);

        __syncthreads();   // all h-gemm reads of sh_h2 done
#pragma unroll
        for (int mt=0; mt<2; mt++)
#pragma unroll
            for (int nt=0; nt<4; nt++) {
                int cc = wc*32 + nt*8 + tg2;
#pragma unroll
                for (int p2=0; p2<2; p2++) {
                    int r = rbase + mt*16 + g + p2*8;
                    float n0 = nn[mt][nt][p2*2], n1 = nn[mt][nt][p2*2+1];
                    float z0 = zz[mt][nt][p2*2], z1 = zz[mt][nt][p2*2+1];
                    float2 hh = unpackbf(*(uint32_t*)&sh_h2[r*APITCH + cc]);
                    float2 hl = unpackbf(*(uint32_t*)&sh_h2[r*APITCH + 128 + cc]);
                    float h0 = (1.f - z0)*n0 + z0*(hh.x + hl.x);
                    float h1 = (1.f - z1)*n1 + z1*(hh.y + hl.y);
                    __nv_bfloat16 s0 = __float2bfloat16(h0), s1 = __float2bfloat16(h1);
                    __nv_bfloat162 hv; hv.x = s0; hv.y = s1;
                    uint32_t hiv = *(uint32_t*)&hv;
                    __nv_bfloat162 lv = __floats2bfloat162_rn(h0 - __bfloat162float(s0),
                                                              h1 - __bfloat162float(s1));
                    uint32_t lov = *(uint32_t*)&lv;
                    *(uint32_t*)&sh_h2[r*APITCH + cc] = hiv;
                    *(uint32_t*)&sh_h2[r*APITCH + 128 + cc] = lov;
                    float* dst = (t < L_-1) ? (g_yseq[t] + ((size_t)(m0+r))*F_ + cc)
                                            : (hT_out   + ((size_t)(m0+r))*F_ + cc);
                    *(float2*)dst = make_float2(h0, h1);
                }
            }
    }
}

// ---------------- loss ----------------
__global__ void lsum_kernel(const int* __restrict__ idxs, const float* __restrict__ y0)
{
    int b = blockIdx.x;
    int t = b % (L_-1), j = (b/(L_-1)) % SUB_, s = b/((L_-1)*SUB_);
    int seq = s*N_ + idxs[j];
    int node = g_walksf[(size_t)seq*L_ + t + 1];
    int o = threadIdx.x;
    __shared__ float red[OR_];
    red[o] = y0[(size_t)node*OR_ + o]; __syncthreads();
    for (int st = OR_/2; st > 0; st >>= 1) { if (o < st) red[o] += red[o+st]; __syncthreads(); }
    if (o == 0) g_part1[b] = red[0];
}

__global__ void lred1_kernel()
{
    __shared__ float red[256];
    int tid = threadIdx.x; float s = 0.f;
    for (int i = tid; i < NB_LOSS; i += 256) s += g_part1[i];
    red[tid] = s; __syncthreads();
    for (int st = 128; st > 0; st >>= 1) { if (tid < st) red[tid] += red[tid+st]; __syncthreads(); }
    if (tid == 0) g_posw = LOSS_CNT / red[0];
}

__global__ void lbce_kernel(const int* __restrict__ idxs, const float* __restrict__ y0,
                            const float* __restrict__ Wss, const float* __restrict__ bss)
{
    int b = blockIdx.x;
    int t = b % (L_-1), j = (b/(L_-1)) % SUB_, s = b/((L_-1)*SUB_);
    int seq = s*N_ + idxs[j];
    __shared__ float yrow[F_];
    int o = threadIdx.x;
    yrow[o]      = g_yseq[t][(size_t)seq*F_ + o];
    yrow[o + 64] = g_yseq[t][(size_t)seq*F_ + o + 64];
    __syncthreads();
    float acc = bss[o];
    const float4* wrp = (const float4*)(Wss + (size_t)o*F_);
#pragma unroll 8
    for (int k = 0; k < F_/4; k++) {
        float4 w = wrp[k];
        acc += yrow[k*4]*w.x + yrow[k*4+1]*w.y + yrow[k*4+2]*w.z + yrow[k*4+3]*w.w;
    }
    int node = g_walksf[(size_t)seq*L_ + t + 1];
    float yt = y0[(size_t)node*OR_ + o];
    float term = g_posw * yt * softplusf(-acc) + (1.f - yt) * softplusf(acc);
    __shared__ float red[OR_];
    red[o] = term; __syncthreads();
    for (int st = OR_/2; st > 0; st >>= 1) { if (o < st) red[o] += red[o+st]; __syncthreads(); }
    if (o == 0) g_part2[b] = red[0];
}

__global__ void lred2_kernel(float* __restrict__ dst)
{
    __shared__ float red[256];
    int tid = threadIdx.x; float s = 0.f;
    for (int i = tid; i < NB_LOSS; i += 256) s += g_part2[i];
    red[tid] = s; __syncthreads();
    for (int st = 128; st > 0; st >>= 1) { if (tid < st) red[tid] += red[tid+st]; __syncthreads(); }
    if (tid == 0) *dst = red[0] / LOSS_CNT;
}

// ---------------- launch ----------------
extern "C" void kernel_launch(void* const* d_in, const int* in_sizes, int n_in,
                              void* d_out, int out_size)
{
    const float* h     = (const float*)d_in[0];
    const float* y0    = (const float*)d_in[1];
    const float* Wih_w = (const float*)d_in[2];
    const float* Whh_w = (const float*)d_in[3];
    const float* bih_w = (const float*)d_in[4];
    const float* bhh_w = (const float*)d_in[5];
    const float* Wih   = (const float*)d_in[6];
    const float* Whh   = (const float*)d_in[7];
    const float* bih   = (const float*)d_in[8];
    const float* bhh   = (const float*)d_in[9];
    const float* W_ss  = (const float*)d_in[10];
    const float* b_ss  = (const float*)d_in[11];
    const int*   walks = (const int*)d_in[12];
    const int*   idxs  = (const int*)d_in[13];
    float* out = (float*)d_out;

    const int SMEM_PT = 33792 + 34816;                 // 68608
    const int SMEM_G1 = 33792 + 69632 + G3_*4 + 256;   // 105216
    const int SMEM_G2 = 104192;
    cudaFuncSetAttribute(pT_kernel,   cudaFuncAttributeMaxDynamicSharedMemorySize, SMEM_PT);
    cudaFuncSetAttribute(gru1_kernel, cudaFuncAttributeMaxDynamicSharedMemorySize, SMEM_G1);
    cudaFuncSetAttribute(gru2_kernel, cudaFuncAttributeMaxDynamicSharedMemorySize, SMEM_G2);

    prep_kernel<<<(SEQ_ + 255)/256, 256>>>(walks);
    wg_kernel<<<1, G3_>>>(Wih_w, bih_w);
    pack_kernel<<<(G3_*F_ + 255)/256, 256>>>(Whh_w, Whh, Wih);
    packh_kernel<<<(NP_*F_ + 255)/256, 256>>>(h);
    pT_kernel<<<dim3(PTILES_, 3), NT_, SMEM_PT>>>(bih);
    gru1_kernel<<<TILES_, NT_, SMEM_G1>>>(bhh_w);
    gru2_kernel<<<TILES_, NT_, SMEM_G2>>>(bhh, out);
    lsum_kernel<<<NB_LOSS, OR_>>>(idxs, y0);
    lred1_kernel<<<1, 256>>>();
    lbce_kernel<<<NB_LOSS, OR_>>>(idxs, y0, W_ss, b_ss);
    lred2_kernel<<<1, 256>>>(out + (out_size - 1));
}